// round 1
// baseline (speedup 1.0000x reference)
#include <cuda_runtime.h>
#include <math.h>

// Problem constants
#define BB 4
#define CC 8
#define HH 192
#define WW 256
#define HWs (HH*WW)

#define GEOM_W 0.01f
#define HUBER_DELTA 0.5f

// Reduction layout
#define NBLK 96          // blocks per batch in accumulate
#define TPB  256
#define PPT  2           // pixels per thread  (NBLK*TPB*PPT == HWs)

// -------- persistent device scratch (no allocations allowed) --------
__device__ float  g_V0 [BB*3*HWs];
__device__ float  g_N0 [BB*3*HWs];
__device__ float  g_dIx[BB*CC*HWs];
__device__ float  g_dIy[BB*CC*HWs];
__device__ double g_part[BB*NBLK*27];
__device__ float  g_pose[BB*16];

// ============================================================
// Precompute kernels
// ============================================================
__global__ void init_pose_kernel(const float* __restrict__ pose_in) {
    int i = threadIdx.x;
    if (i < BB*16) g_pose[i] = pose_in[i];
}

__global__ void vertex_kernel(const float* __restrict__ depth0,
                              const float* __restrict__ intr) {
    int idx = blockIdx.x * blockDim.x + threadIdx.x;
    if (idx >= BB*HWs) return;
    int b = idx / HWs, p = idx % HWs;
    int h = p / WW, w = p % WW;
    float fx = intr[b*4+0], fy = intr[b*4+1], cx = intr[b*4+2], cy = intr[b*4+3];
    float px = ((float)w - cx) / fx;
    float py = ((float)h - cy) / fy;
    float d0 = depth0[idx];
    g_V0[(b*3+0)*HWs + p] = px * d0;
    g_V0[(b*3+1)*HWs + p] = py * d0;
    g_V0[(b*3+2)*HWs + p] = d0;
}

__global__ void normal_kernel() {
    int idx = blockIdx.x * blockDim.x + threadIdx.x;
    if (idx >= BB*HWs) return;
    int b = idx / HWs, p = idx % HWs;
    int h = p / WW, w = p % WW;
    int xm = (w > 0)      ? w-1 : 0;
    int xp = (w < WW-1)   ? w+1 : WW-1;
    int ym = (h > 0)      ? h-1 : 0;
    int yp = (h < HH-1)   ? h+1 : HH-1;
    const float* V = &g_V0[b*3*HWs];
    float dx[3], dy[3];
    #pragma unroll
    for (int c = 0; c < 3; c++) {
        dx[c] = (V[c*HWs + h*WW + xp] - V[c*HWs + h*WW + xm]) * 0.5f;
        dy[c] = (V[c*HWs + yp*WW + w] - V[c*HWs + ym*WW + w]) * 0.5f;
    }
    // n = dx x dy
    float nx = dx[1]*dy[2] - dx[2]*dy[1];
    float ny = dx[2]*dy[0] - dx[0]*dy[2];
    float nz = dx[0]*dy[1] - dx[1]*dy[0];
    float inv = 1.0f / sqrtf(nx*nx + ny*ny + nz*nz + 1e-12f);
    g_N0[(b*3+0)*HWs + p] = nx * inv;
    g_N0[(b*3+1)*HWs + p] = ny * inv;
    g_N0[(b*3+2)*HWs + p] = nz * inv;
}

__global__ void grad_kernel(const float* __restrict__ I0) {
    int idx = blockIdx.x * blockDim.x + threadIdx.x;
    if (idx >= BB*CC*HWs) return;
    int p = idx % HWs;
    int h = p / WW, w = p % WW;
    int base = idx - p;
    int xm = (w > 0)    ? w-1 : 0;
    int xp = (w < WW-1) ? w+1 : WW-1;
    int ym = (h > 0)    ? h-1 : 0;
    int yp = (h < HH-1) ? h+1 : HH-1;
    g_dIx[idx] = (I0[base + h*WW + xp] - I0[base + h*WW + xm]) * 0.5f;
    g_dIy[idx] = (I0[base + yp*WW + w] - I0[base + ym*WW + w]) * 0.5f;
}

// ============================================================
// Accumulate kernel: per-pixel residuals/Jacobians -> partial JtJ/rhs
// ============================================================
__device__ __forceinline__ void accrow(float* acc, const float* J, float r) {
    float ar  = fabsf(r);
    float wgt = (ar <= HUBER_DELTA) ? 1.0f : HUBER_DELTA / fmaxf(ar, 1e-12f);
    float wr  = wgt * r;
    int k = 0;
    #pragma unroll
    for (int i = 0; i < 6; i++) {
        float wJi = wgt * J[i];
        #pragma unroll
        for (int j = i; j < 6; j++) acc[k++] += wJi * J[j];
        acc[21+i] += wr * J[i];
    }
}

__global__ void __launch_bounds__(TPB)
accumulate_kernel(const float* __restrict__ I0,
                  const float* __restrict__ I1,
                  const float* __restrict__ depth0,
                  const float* __restrict__ depth1,
                  const float* __restrict__ intr) {
    int b = blockIdx.y;
    float fx = intr[b*4+0], fy = intr[b*4+1], cx = intr[b*4+2], cy = intr[b*4+3];
    // pose
    float R00 = g_pose[b*16+0], R01 = g_pose[b*16+1], R02 = g_pose[b*16+2],  t0 = g_pose[b*16+3];
    float R10 = g_pose[b*16+4], R11 = g_pose[b*16+5], R12 = g_pose[b*16+6],  t1 = g_pose[b*16+7];
    float R20 = g_pose[b*16+8], R21 = g_pose[b*16+9], R22 = g_pose[b*16+10], t2 = g_pose[b*16+11];

    float acc[27];
    #pragma unroll
    for (int i = 0; i < 27; i++) acc[i] = 0.0f;

    const float* V0b = &g_V0[b*3*HWs];
    const float* N0b = &g_N0[b*3*HWs];

    for (int k = 0; k < PPT; k++) {
        int p  = (blockIdx.x * PPT + k) * TPB + threadIdx.x;
        int hh = p / WW, wwp = p % WW;
        float d0 = depth0[b*HWs + p];
        float d1 = depth1[b*HWs + p];
        // V1 recomputed on the fly
        float pxv = ((float)wwp - cx) / fx;
        float pyv = ((float)hh  - cy) / fy;
        float v1x = pxv * d1, v1y = pyv * d1, v1z = d1;

        float x = R00*v1x + R01*v1y + R02*v1z + t0;
        float y = R10*v1x + R11*v1y + R12*v1z + t1;
        float z = R20*v1x + R21*v1y + R22*v1z + t2;

        bool valid0 = z > 1e-8f;
        float zs = (fabsf(z) > 1e-8f) ? z : 1e-8f;
        float u = fx * x / zs + cx;
        float v = fy * y / zs + cy;
        bool inb = (u > 0.0f) && (u < (float)(WW-1)) && (v > 0.0f) && (v < (float)(HH-1));
        bool valid = inb && valid0 && (d0 > 0.0f) && (d1 > 0.0f);
        if (!valid) continue;

        // bilinear setup (all 4 taps guaranteed in-bounds for valid pixels)
        float u0f = floorf(u), v0f = floorf(v);
        float du = u - u0f, dv = v - v0f;
        int iu0 = (int)u0f, iv0 = (int)v0f;
        int o00 = iv0*WW + iu0;
        int o01 = o00 + 1;
        int o10 = o00 + WW;
        int o11 = o10 + 1;
        float wa = (1.0f-du)*(1.0f-dv);
        float wb = du*(1.0f-dv);
        float wc = (1.0f-du)*dv;
        float wd = du*dv;
        #define SAMP(arr) (wa*(arr)[o00] + wb*(arr)[o01] + wc*(arr)[o10] + wd*(arr)[o11])

        // ---------------- ICP row ----------------
        {
            float rVx = SAMP(V0b);           float rVy = SAMP(V0b + HWs);   float rVz = SAMP(V0b + 2*HWs);
            float rNx = SAMP(N0b);           float rNy = SAMP(N0b + HWs);   float rNz = SAMP(N0b + 2*HWs);
            float dx_ = x - rVx, dy_ = y - rVy, dz_ = z - rVz;
            float dn = sqrtf(dx_*dx_ + dy_*dy_ + dz_*dz_ + 1e-12f);
            bool occ = dn > 0.1f;   // inviews == inb == true here
            float res_raw = rNx*dx_ + rNy*dy_ + rNz*dz_;
            // NtC = R^T * rN
            float N0_ = rNx*R00 + rNy*R10 + rNz*R20;
            float N1_ = rNx*R01 + rNy*R11 + rNz*R21;
            float N2_ = rNx*R02 + rNy*R12 + rNz*R22;
            // sigma
            const float focal = 525.0f, sxy = 5.5f, sdisp = 0.4f, baseline = 1.2f;
            float sd0 = d1 / focal * sxy;
            float sd2 = d1 * d1 * sdisp / (focal * baseline);
            float cov = (N0_*N0_ + N1_*N1_) * (sd0*sd0) + N2_*N2_*(sd2*sd2);
            float sigma = sqrtf(cov + 1e-8f);
            float sden = sigma + 1e-8f;
            float res = res_raw / sden;
            if (occ) res = 1e-6f;
            // Jrot = NtC^T * skew(V1)
            float Jr0 = N1_*v1z - N2_*v1y;
            float Jr1 = -N0_*v1z + N2_*v1x;
            float Jr2 = N0_*v1y - N1_*v1x;
            float Ji[6];
            float s = GEOM_W / sden;
            Ji[0] = -Jr0 * s;  Ji[1] = -Jr1 * s;  Ji[2] = -Jr2 * s;
            Ji[3] =  N0_ * s;  Ji[4] =  N1_ * s;  Ji[5] =  N2_ * s;
            float ri = -GEOM_W * res;
            accrow(acc, Ji, ri);
        }

        // ---------------- photometric rows ----------------
        float a  = fx / zs;
        float bq = -fx * x / (zs*zs);
        float c_ = fy / zs;
        float dq = -fy * y / (zs*zs);
        float Jw0[6] = { bq*y,           a*z - bq*x, -a*y,  a,    0.0f, bq };
        float Jw1[6] = { -c_*z + dq*y,  -dq*x,        c_*x, 0.0f, c_,   dq };

        #pragma unroll
        for (int c = 0; c < CC; c++) {
            const float* I0c = I0    + ((size_t)b*CC + c)*HWs;
            const float* gxc = g_dIx + ((size_t)b*CC + c)*HWs;
            const float* gyc = g_dIy + ((size_t)b*CC + c)*HWs;
            float I0w = SAMP(I0c);
            float gx  = SAMP(gxc);
            float gy  = SAMP(gyc);
            float r = I1[((size_t)b*CC + c)*HWs + p] - I0w;
            float J[6];
            #pragma unroll
            for (int i = 0; i < 6; i++) J[i] = gx*Jw0[i] + gy*Jw1[i];
            accrow(acc, J, r);
        }
        #undef SAMP
    }

    // -------- block reduction (deterministic order) --------
    __shared__ double sred[TPB/32][27];
    int warp = threadIdx.x >> 5, lane = threadIdx.x & 31;
    for (int i = 0; i < 27; i++) {
        double val = (double)acc[i];
        #pragma unroll
        for (int o = 16; o > 0; o >>= 1)
            val += __shfl_down_sync(0xffffffffu, val, o);
        if (lane == 0) sred[warp][i] = val;
    }
    __syncthreads();
    if (threadIdx.x < 27) {
        double s = 0.0;
        #pragma unroll
        for (int w2 = 0; w2 < TPB/32; w2++) s += sred[w2][threadIdx.x];
        g_part[((size_t)b*NBLK + blockIdx.x)*27 + threadIdx.x] = s;
    }
}

// ============================================================
// Solve 6x6, SE3 exp, pose composition (1 thread per batch)
// ============================================================
__global__ void solve_kernel() {
    int b = threadIdx.x;
    if (b >= BB) return;

    double a[27];
    for (int i = 0; i < 27; i++) a[i] = 0.0;
    for (int blk = 0; blk < NBLK; blk++) {
        const double* pp = &g_part[((size_t)b*NBLK + blk)*27];
        for (int i = 0; i < 27; i++) a[i] += pp[i];
    }

    double M[6][7];
    {
        int k = 0;
        for (int i = 0; i < 6; i++)
            for (int j = i; j < 6; j++) { M[i][j] = a[k]; M[j][i] = a[k]; k++; }
        for (int i = 0; i < 6; i++) { M[i][i] += 1e-6; M[i][6] = a[21+i]; }
    }
    // Gaussian elimination with partial pivoting
    for (int col = 0; col < 6; col++) {
        int piv = col; double mx = fabs(M[col][col]);
        for (int r = col+1; r < 6; r++) {
            double v2 = fabs(M[r][col]);
            if (v2 > mx) { mx = v2; piv = r; }
        }
        if (piv != col)
            for (int cc2 = col; cc2 < 7; cc2++) { double tmp = M[col][cc2]; M[col][cc2] = M[piv][cc2]; M[piv][cc2] = tmp; }
        double inv = 1.0 / M[col][col];
        for (int r = col+1; r < 6; r++) {
            double f = M[r][col] * inv;
            for (int cc2 = col; cc2 < 7; cc2++) M[r][cc2] -= f * M[col][cc2];
        }
    }
    double xi[6];
    for (int i = 5; i >= 0; i--) {
        double s = M[i][6];
        for (int j = i+1; j < 6; j++) s -= M[i][j] * xi[j];
        xi[i] = s / M[i][i];
    }

    // SE3 exp
    double w0 = xi[0], w1 = xi[1], w2 = xi[2];
    double vv0 = xi[3], vv1 = xi[4], vv2 = xi[5];
    double th2 = w0*w0 + w1*w1 + w2*w2;
    double A, Bc, Cc;
    if (th2 < 1e-8) {
        A  = 1.0 - th2/6.0;
        Bc = 0.5 - th2/24.0;
        Cc = 1.0/6.0 - th2/120.0;
    } else {
        double th = sqrt(th2);
        A  = sin(th) / th;
        Bc = (1.0 - cos(th)) / th2;
        Cc = (th - sin(th)) / (th2 * th);
    }
    double K[3][3] = {{0.0,-w2,w1},{w2,0.0,-w0},{-w1,w0,0.0}};
    double K2[3][3];
    for (int i = 0; i < 3; i++)
        for (int j = 0; j < 3; j++)
            K2[i][j] = K[i][0]*K[0][j] + K[i][1]*K[1][j] + K[i][2]*K[2][j];
    double Re[3][3], Vm[3][3];
    for (int i = 0; i < 3; i++)
        for (int j = 0; j < 3; j++) {
            double I_ = (i == j) ? 1.0 : 0.0;
            Re[i][j] = I_ + A*K[i][j] + Bc*K2[i][j];
            Vm[i][j] = I_ + Bc*K[i][j] + Cc*K2[i][j];
        }
    double te[3];
    for (int i = 0; i < 3; i++)
        te[i] = Vm[i][0]*vv0 + Vm[i][1]*vv1 + Vm[i][2]*vv2;

    // compose: pose_new = Texp @ pose_old
    double Ro[3][3], to[3];
    for (int i = 0; i < 3; i++) {
        for (int j = 0; j < 3; j++) Ro[i][j] = (double)g_pose[b*16 + i*4 + j];
        to[i] = (double)g_pose[b*16 + i*4 + 3];
    }
    double Rn[3][3], tn[3];
    for (int i = 0; i < 3; i++) {
        for (int j = 0; j < 3; j++)
            Rn[i][j] = Re[i][0]*Ro[0][j] + Re[i][1]*Ro[1][j] + Re[i][2]*Ro[2][j];
        tn[i] = Re[i][0]*to[0] + Re[i][1]*to[1] + Re[i][2]*to[2] + te[i];
    }
    for (int i = 0; i < 3; i++) {
        for (int j = 0; j < 3; j++) g_pose[b*16 + i*4 + j] = (float)Rn[i][j];
        g_pose[b*16 + i*4 + 3] = (float)tn[i];
    }
    g_pose[b*16 + 12] = 0.0f; g_pose[b*16 + 13] = 0.0f;
    g_pose[b*16 + 14] = 0.0f; g_pose[b*16 + 15] = 1.0f;
}

__global__ void copyout_kernel(float* __restrict__ out) {
    int i = threadIdx.x;
    if (i < BB*16) out[i] = g_pose[i];
}

// ============================================================
extern "C" void kernel_launch(void* const* d_in, const int* in_sizes, int n_in,
                              void* d_out, int out_size) {
    const float* pose_in = (const float*)d_in[0];
    const float* I0      = (const float*)d_in[1];
    const float* I1      = (const float*)d_in[2];
    // d_in[3], d_in[4] = invD0/invD1 (unused by the reference math)
    const float* intr    = (const float*)d_in[5];
    const float* depth0  = (const float*)d_in[6];
    const float* depth1  = (const float*)d_in[7];
    float* out = (float*)d_out;

    init_pose_kernel<<<1, 64>>>(pose_in);
    vertex_kernel<<<(BB*HWs + 255)/256, 256>>>(depth0, intr);
    normal_kernel<<<(BB*HWs + 255)/256, 256>>>();
    grad_kernel<<<(BB*CC*HWs + 255)/256, 256>>>(I0);

    dim3 agrid(NBLK, BB);
    for (int it = 0; it < 3; it++) {
        accumulate_kernel<<<agrid, TPB>>>(I0, I1, depth0, depth1, intr);
        solve_kernel<<<1, 32>>>();
    }
    copyout_kernel<<<1, 64>>>(out);
}

// round 2
// speedup vs baseline: 1.7550x; 1.7550x over previous
#include <cuda_runtime.h>
#include <math.h>

// Problem constants
#define BB 4
#define CC 8
#define HH 192
#define WW 256
#define HWs (HH*WW)

#define GEOM_W 0.01f
#define HUBER_DELTA 0.5f

// Reduction layout
#define NBLK 192         // blocks per batch in accumulate
#define TPB  256         // NBLK*TPB == HWs

// -------- persistent device scratch (no allocations allowed) --------
__device__ float  g_pack[(size_t)BB*HWs*24];  // per pixel: (I0,gx,gy) x 8 channels
__device__ float  g_vn  [(size_t)BB*HWs*8];   // per pixel: V0x,V0y,V0z,N0x,N0y,N0z,0,0
__device__ double g_part[BB*NBLK*27];
__device__ float  g_pose[BB*16];

// ============================================================
// Precompute kernels
// ============================================================
__global__ void init_pose_kernel(const float* __restrict__ pose_in) {
    int i = threadIdx.x;
    if (i < BB*16) g_pose[i] = pose_in[i];
}

// V0 + N0 packed, computed directly from depth0 (vertices are analytic in depth)
__global__ void vnpack_kernel(const float* __restrict__ depth0,
                              const float* __restrict__ intr) {
    int idx = blockIdx.x * blockDim.x + threadIdx.x;
    if (idx >= BB*HWs) return;
    int b = idx / HWs, p = idx % HWs;
    int h = p / WW, w = p % WW;
    float fx = intr[b*4+0], fy = intr[b*4+1], cx = intr[b*4+2], cy = intr[b*4+3];
    float invfx = 1.0f/fx, invfy = 1.0f/fy;

    float px = ((float)w - cx) * invfx;
    float py = ((float)h - cy) * invfy;
    const float* D = depth0 + (size_t)b*HWs;
    float d  = D[p];

    int xm = (w > 0)    ? w-1 : 0;
    int xp = (w < WW-1) ? w+1 : WW-1;
    int ym = (h > 0)    ? h-1 : 0;
    int yp = (h < HH-1) ? h+1 : HH-1;
    float dxm = D[h*WW + xm], dxp = D[h*WW + xp];
    float dym = D[ym*WW + w], dyp = D[yp*WW + w];
    float pxm = ((float)xm - cx) * invfx, pxp = ((float)xp - cx) * invfx;
    float pym = ((float)ym - cy) * invfy, pyp = ((float)yp - cy) * invfy;

    // central diffs of the vertex map
    float dxv0 = 0.5f*(pxp*dxp - pxm*dxm);
    float dxv1 = 0.5f*py*(dxp - dxm);
    float dxv2 = 0.5f*(dxp - dxm);
    float dyv0 = 0.5f*px*(dyp - dym);
    float dyv1 = 0.5f*(pyp*dyp - pym*dym);
    float dyv2 = 0.5f*(dyp - dym);

    float nx = dxv1*dyv2 - dxv2*dyv1;
    float ny = dxv2*dyv0 - dxv0*dyv2;
    float nz = dxv0*dyv1 - dxv1*dyv0;
    float inv = 1.0f / sqrtf(nx*nx + ny*ny + nz*nz + 1e-12f);

    float4* out = (float4*)g_vn;
    out[(size_t)idx*2 + 0] = make_float4(px*d, py*d, d, nx*inv);
    out[(size_t)idx*2 + 1] = make_float4(ny*inv, nz*inv, 0.0f, 0.0f);
}

// (I0, dI0x, dI0y) per channel packed per pixel
__global__ void gradpack_kernel(const float* __restrict__ I0) {
    int idx = blockIdx.x * blockDim.x + threadIdx.x;
    if (idx >= BB*HWs) return;
    int b = idx / HWs, p = idx % HWs;
    int h = p / WW, w = p % WW;
    int xm = (w > 0)    ? w-1 : 0;
    int xp = (w < WW-1) ? w+1 : WW-1;
    int ym = (h > 0)    ? h-1 : 0;
    int yp = (h < HH-1) ? h+1 : HH-1;

    float pk[24];
    #pragma unroll
    for (int c = 0; c < CC; c++) {
        const float* P = I0 + ((size_t)b*CC + c)*HWs;
        pk[c*3+0] = P[p];
        pk[c*3+1] = (P[h*WW + xp] - P[h*WW + xm]) * 0.5f;
        pk[c*3+2] = (P[yp*WW + w] - P[ym*WW + w]) * 0.5f;
    }
    float4* out = (float4*)(g_pack + (size_t)idx*24);
    #pragma unroll
    for (int j = 0; j < 6; j++)
        out[j] = make_float4(pk[4*j], pk[4*j+1], pk[4*j+2], pk[4*j+3]);
}

// ============================================================
// Accumulate kernel
// ============================================================
__global__ void __launch_bounds__(TPB)
accumulate_kernel(const float* __restrict__ I1,
                  const float* __restrict__ depth0,
                  const float* __restrict__ depth1,
                  const float* __restrict__ intr) {
    int b = blockIdx.y;
    float fx = intr[b*4+0], fy = intr[b*4+1], cx = intr[b*4+2], cy = intr[b*4+3];
    float R00 = g_pose[b*16+0], R01 = g_pose[b*16+1], R02 = g_pose[b*16+2],  t0 = g_pose[b*16+3];
    float R10 = g_pose[b*16+4], R11 = g_pose[b*16+5], R12 = g_pose[b*16+6],  t1 = g_pose[b*16+7];
    float R20 = g_pose[b*16+8], R21 = g_pose[b*16+9], R22 = g_pose[b*16+10], t2 = g_pose[b*16+11];

    float acc[27];
    #pragma unroll
    for (int i = 0; i < 27; i++) acc[i] = 0.0f;

    int p  = blockIdx.x * TPB + threadIdx.x;
    int hh = p / WW, wwp = p % WW;
    float d0 = depth0[(size_t)b*HWs + p];
    float d1 = depth1[(size_t)b*HWs + p];
    float pxv = ((float)wwp - cx) / fx;
    float pyv = ((float)hh  - cy) / fy;
    float v1x = pxv * d1, v1y = pyv * d1, v1z = d1;

    float x = R00*v1x + R01*v1y + R02*v1z + t0;
    float y = R10*v1x + R11*v1y + R12*v1z + t1;
    float z = R20*v1x + R21*v1y + R22*v1z + t2;

    bool valid0 = z > 1e-8f;
    float zs = (fabsf(z) > 1e-8f) ? z : 1e-8f;
    float u = fx * x / zs + cx;
    float v = fy * y / zs + cy;
    bool inb = (u > 0.0f) && (u < (float)(WW-1)) && (v > 0.0f) && (v < (float)(HH-1));
    bool valid = inb && valid0 && (d0 > 0.0f) && (d1 > 0.0f);

    if (valid) {
        float u0f = floorf(u), v0f = floorf(v);
        float du = u - u0f, dv = v - v0f;
        int iu0 = (int)u0f, iv0 = (int)v0f;
        int offs[4];
        offs[0] = iv0*WW + iu0;
        offs[1] = offs[0] + 1;
        offs[2] = offs[0] + WW;
        offs[3] = offs[2] + 1;
        float wt4[4];
        wt4[0] = (1.0f-du)*(1.0f-dv);
        wt4[1] = du*(1.0f-dv);
        wt4[2] = (1.0f-du)*dv;
        wt4[3] = du*dv;

        // ---- vectorized bilinear sampling of packed maps ----
        const float4* pk4 = (const float4*)(g_pack + (size_t)b*HWs*24);
        const float4* vn4 = (const float4*)(g_vn   + (size_t)b*HWs*8);
        float4 s[6];
        float4 sv[2];
        #pragma unroll
        for (int j = 0; j < 6; j++) s[j] = make_float4(0,0,0,0);
        sv[0] = make_float4(0,0,0,0); sv[1] = make_float4(0,0,0,0);

        #pragma unroll
        for (int t = 0; t < 4; t++) {
            float wt = wt4[t];
            const float4* q = pk4 + (size_t)offs[t]*6;
            #pragma unroll
            for (int j = 0; j < 6; j++) {
                float4 qq = q[j];
                s[j].x += wt*qq.x; s[j].y += wt*qq.y; s[j].z += wt*qq.z; s[j].w += wt*qq.w;
            }
            const float4* qv = vn4 + (size_t)offs[t]*2;
            float4 a0 = qv[0], a1 = qv[1];
            sv[0].x += wt*a0.x; sv[0].y += wt*a0.y; sv[0].z += wt*a0.z; sv[0].w += wt*a0.w;
            sv[1].x += wt*a1.x; sv[1].y += wt*a1.y;
        }

        // ---------------- ICP row ----------------
        {
            float rVx = sv[0].x, rVy = sv[0].y, rVz = sv[0].z;
            float rNx = sv[0].w, rNy = sv[1].x, rNz = sv[1].y;
            float dx_ = x - rVx, dy_ = y - rVy, dz_ = z - rVz;
            float dn = sqrtf(dx_*dx_ + dy_*dy_ + dz_*dz_ + 1e-12f);
            bool occ = dn > 0.1f;
            float res_raw = rNx*dx_ + rNy*dy_ + rNz*dz_;
            float N0_ = rNx*R00 + rNy*R10 + rNz*R20;
            float N1_ = rNx*R01 + rNy*R11 + rNz*R21;
            float N2_ = rNx*R02 + rNy*R12 + rNz*R22;
            const float focal = 525.0f, sxy = 5.5f, sdisp = 0.4f, baseline = 1.2f;
            float sd0 = d1 / focal * sxy;
            float sd2 = d1 * d1 * sdisp / (focal * baseline);
            float cov = (N0_*N0_ + N1_*N1_) * (sd0*sd0) + N2_*N2_*(sd2*sd2);
            float sigma = sqrtf(cov + 1e-8f);
            float sden = sigma + 1e-8f;
            float res = res_raw / sden;
            if (occ) res = 1e-6f;
            float Jr0 =  N1_*v1z - N2_*v1y;
            float Jr1 = -N0_*v1z + N2_*v1x;
            float Jr2 =  N0_*v1y - N1_*v1x;
            float sc = GEOM_W / sden;
            float Ji[6];
            Ji[0] = -Jr0*sc;  Ji[1] = -Jr1*sc;  Ji[2] = -Jr2*sc;
            Ji[3] =  N0_*sc;  Ji[4] =  N1_*sc;  Ji[5] =  N2_*sc;
            float ri = -GEOM_W * res;
            float ar  = fabsf(ri);
            float wgt = (ar <= HUBER_DELTA) ? 1.0f : HUBER_DELTA / fmaxf(ar, 1e-12f);
            float wr  = wgt * ri;
            int k = 0;
            #pragma unroll
            for (int i = 0; i < 6; i++) {
                float wJi = wgt * Ji[i];
                #pragma unroll
                for (int j = i; j < 6; j++) acc[k++] += wJi * Ji[j];
                acc[21+i] += wr * Ji[i];
            }
        }

        // ---------------- photometric rows (factored) ----------------
        float a  = fx / zs;
        float bq = -fx * x / (zs*zs);
        float c_ = fy / zs;
        float dq = -fy * y / (zs*zs);
        float Jw0[6] = { bq*y,          a*z - bq*x, -a*y,  a,    0.0f, bq };
        float Jw1[6] = { -c_*z + dq*y, -dq*x,        c_*x, 0.0f, c_,   dq };

        const float* Sf = (const float*)s;
        float A2 = 0.0f, Bq2 = 0.0f, C2 = 0.0f, Dd = 0.0f, Ee = 0.0f;
        #pragma unroll
        for (int c = 0; c < CC; c++) {
            float I0w = Sf[c*3+0];
            float gx  = Sf[c*3+1];
            float gy  = Sf[c*3+2];
            float r   = I1[((size_t)b*CC + c)*HWs + p] - I0w;
            float ar  = fabsf(r);
            float wgt = (ar <= HUBER_DELTA) ? 1.0f : HUBER_DELTA / fmaxf(ar, 1e-12f);
            float wgx = wgt * gx;
            float wgy = wgt * gy;
            A2 += wgx * gx;
            Bq2 += wgx * gy;
            C2 += wgy * gy;
            Dd += wgx * r;
            Ee += wgy * r;
        }
        // rank-2 update
        int k = 0;
        #pragma unroll
        for (int i = 0; i < 6; i++) {
            float a0 = A2*Jw0[i] + Bq2*Jw1[i];
            float a1 = Bq2*Jw0[i] + C2*Jw1[i];
            #pragma unroll
            for (int j = i; j < 6; j++) acc[k++] += a0*Jw0[j] + a1*Jw1[j];
            acc[21+i] += Dd*Jw0[i] + Ee*Jw1[i];
        }
    }

    // -------- block reduction (deterministic order) --------
    __shared__ double sred[TPB/32][27];
    int warp = threadIdx.x >> 5, lane = threadIdx.x & 31;
    #pragma unroll
    for (int i = 0; i < 27; i++) {
        double val = (double)acc[i];
        #pragma unroll
        for (int o = 16; o > 0; o >>= 1)
            val += __shfl_down_sync(0xffffffffu, val, o);
        if (lane == 0) sred[warp][i] = val;
    }
    __syncthreads();
    if (threadIdx.x < 27) {
        double ss = 0.0;
        #pragma unroll
        for (int w2 = 0; w2 < TPB/32; w2++) ss += sred[w2][threadIdx.x];
        g_part[((size_t)b*NBLK + blockIdx.x)*27 + threadIdx.x] = ss;
    }
}

// ============================================================
// Solve 6x6, SE3 exp, pose composition (one block per batch)
// ============================================================
__global__ void solve_kernel() {
    int b = blockIdx.x;
    __shared__ double sa[27];
    if (threadIdx.x < 27) {
        double s = 0.0;
        for (int blk = 0; blk < NBLK; blk++)
            s += g_part[((size_t)b*NBLK + blk)*27 + threadIdx.x];
        sa[threadIdx.x] = s;
    }
    __syncthreads();
    if (threadIdx.x != 0) return;

    double M[6][7];
    {
        int k = 0;
        for (int i = 0; i < 6; i++)
            for (int j = i; j < 6; j++) { M[i][j] = sa[k]; M[j][i] = sa[k]; k++; }
        for (int i = 0; i < 6; i++) { M[i][i] += 1e-6; M[i][6] = sa[21+i]; }
    }
    for (int col = 0; col < 6; col++) {
        int piv = col; double mx = fabs(M[col][col]);
        for (int r = col+1; r < 6; r++) {
            double v2 = fabs(M[r][col]);
            if (v2 > mx) { mx = v2; piv = r; }
        }
        if (piv != col)
            for (int cc2 = col; cc2 < 7; cc2++) { double tmp = M[col][cc2]; M[col][cc2] = M[piv][cc2]; M[piv][cc2] = tmp; }
        double inv = 1.0 / M[col][col];
        for (int r = col+1; r < 6; r++) {
            double f = M[r][col] * inv;
            for (int cc2 = col; cc2 < 7; cc2++) M[r][cc2] -= f * M[col][cc2];
        }
    }
    double xi[6];
    for (int i = 5; i >= 0; i--) {
        double s = M[i][6];
        for (int j = i+1; j < 6; j++) s -= M[i][j] * xi[j];
        xi[i] = s / M[i][i];
    }

    double w0 = xi[0], w1 = xi[1], w2 = xi[2];
    double vv0 = xi[3], vv1 = xi[4], vv2 = xi[5];
    double th2 = w0*w0 + w1*w1 + w2*w2;
    double A, Bc, Cc;
    if (th2 < 1e-8) {
        A  = 1.0 - th2/6.0;
        Bc = 0.5 - th2/24.0;
        Cc = 1.0/6.0 - th2/120.0;
    } else {
        double th = sqrt(th2);
        A  = sin(th) / th;
        Bc = (1.0 - cos(th)) / th2;
        Cc = (th - sin(th)) / (th2 * th);
    }
    double K[3][3] = {{0.0,-w2,w1},{w2,0.0,-w0},{-w1,w0,0.0}};
    double K2[3][3];
    for (int i = 0; i < 3; i++)
        for (int j = 0; j < 3; j++)
            K2[i][j] = K[i][0]*K[0][j] + K[i][1]*K[1][j] + K[i][2]*K[2][j];
    double Re[3][3], Vm[3][3];
    for (int i = 0; i < 3; i++)
        for (int j = 0; j < 3; j++) {
            double I_ = (i == j) ? 1.0 : 0.0;
            Re[i][j] = I_ + A*K[i][j] + Bc*K2[i][j];
            Vm[i][j] = I_ + Bc*K[i][j] + Cc*K2[i][j];
        }
    double te[3];
    for (int i = 0; i < 3; i++)
        te[i] = Vm[i][0]*vv0 + Vm[i][1]*vv1 + Vm[i][2]*vv2;

    double Ro[3][3], to[3];
    for (int i = 0; i < 3; i++) {
        for (int j = 0; j < 3; j++) Ro[i][j] = (double)g_pose[b*16 + i*4 + j];
        to[i] = (double)g_pose[b*16 + i*4 + 3];
    }
    double Rn[3][3], tn[3];
    for (int i = 0; i < 3; i++) {
        for (int j = 0; j < 3; j++)
            Rn[i][j] = Re[i][0]*Ro[0][j] + Re[i][1]*Ro[1][j] + Re[i][2]*Ro[2][j];
        tn[i] = Re[i][0]*to[0] + Re[i][1]*to[1] + Re[i][2]*to[2] + te[i];
    }
    for (int i = 0; i < 3; i++) {
        for (int j = 0; j < 3; j++) g_pose[b*16 + i*4 + j] = (float)Rn[i][j];
        g_pose[b*16 + i*4 + 3] = (float)tn[i];
    }
    g_pose[b*16 + 12] = 0.0f; g_pose[b*16 + 13] = 0.0f;
    g_pose[b*16 + 14] = 0.0f; g_pose[b*16 + 15] = 1.0f;
}

__global__ void copyout_kernel(float* __restrict__ out) {
    int i = threadIdx.x;
    if (i < BB*16) out[i] = g_pose[i];
}

// ============================================================
extern "C" void kernel_launch(void* const* d_in, const int* in_sizes, int n_in,
                              void* d_out, int out_size) {
    const float* pose_in = (const float*)d_in[0];
    const float* I0      = (const float*)d_in[1];
    const float* I1      = (const float*)d_in[2];
    const float* intr    = (const float*)d_in[5];
    const float* depth0  = (const float*)d_in[6];
    const float* depth1  = (const float*)d_in[7];
    float* out = (float*)d_out;

    init_pose_kernel<<<1, 64>>>(pose_in);
    vnpack_kernel<<<(BB*HWs + 255)/256, 256>>>(depth0, intr);
    gradpack_kernel<<<(BB*HWs + 255)/256, 256>>>(I0);

    dim3 agrid(NBLK, BB);
    for (int it = 0; it < 3; it++) {
        accumulate_kernel<<<agrid, TPB>>>(I1, depth0, depth1, intr);
        solve_kernel<<<BB, 32>>>();
    }
    copyout_kernel<<<1, 64>>>(out);
}

// round 4
// speedup vs baseline: 5.5894x; 3.1848x over previous
#include <cuda_runtime.h>
#include <math.h>

// Problem constants
#define BB 4
#define CC 8
#define HH 192
#define WW 256
#define HWs (HH*WW)

#define GEOM_W 0.01f
#define HUBER_DELTA 0.5f

// Reduction layout
#define NBLK 96          // blocks per batch
#define TPB  256
#define PPT  2           // NBLK*TPB*PPT == HWs

// -------- persistent device scratch (planar / SoA) --------
__device__ float4 g_ip  [(size_t)BB*CC*HWs];  // per channel plane: (I0, gx, gy, 0)
__device__ float4 g_v0  [(size_t)BB*HWs];     // plane: V0x,V0y,V0z,N0x
__device__ float2 g_n0  [(size_t)BB*HWs];     // plane: N0y,N0z
__device__ double g_part[BB*NBLK*27];
__device__ float  g_pose[BB*16];

// ============================================================
__global__ void init_pose_kernel(const float* __restrict__ pose_in) {
    int i = threadIdx.x;
    if (i < BB*16) g_pose[i] = pose_in[i];
}

// V0 + N0 planes, computed directly from depth0
__global__ void vnpack_kernel(const float* __restrict__ depth0,
                              const float* __restrict__ intr) {
    int idx = blockIdx.x * blockDim.x + threadIdx.x;
    if (idx >= BB*HWs) return;
    int b = idx / HWs, p = idx % HWs;
    int h = p / WW, w = p % WW;
    float fx = intr[b*4+0], fy = intr[b*4+1], cx = intr[b*4+2], cy = intr[b*4+3];
    float invfx = 1.0f/fx, invfy = 1.0f/fy;

    float px = ((float)w - cx) * invfx;
    float py = ((float)h - cy) * invfy;
    const float* D = depth0 + (size_t)b*HWs;
    float d  = D[p];

    int xm = (w > 0)    ? w-1 : 0;
    int xp = (w < WW-1) ? w+1 : WW-1;
    int ym = (h > 0)    ? h-1 : 0;
    int yp = (h < HH-1) ? h+1 : HH-1;
    float dxm = D[h*WW + xm], dxp = D[h*WW + xp];
    float dym = D[ym*WW + w], dyp = D[yp*WW + w];
    float pxm = ((float)xm - cx) * invfx, pxp = ((float)xp - cx) * invfx;
    float pym = ((float)ym - cy) * invfy, pyp = ((float)yp - cy) * invfy;

    float dxv0 = 0.5f*(pxp*dxp - pxm*dxm);
    float dxv1 = 0.5f*py*(dxp - dxm);
    float dxv2 = 0.5f*(dxp - dxm);
    float dyv0 = 0.5f*px*(dyp - dym);
    float dyv1 = 0.5f*(pyp*dyp - pym*dym);
    float dyv2 = 0.5f*(dyp - dym);

    float nx = dxv1*dyv2 - dxv2*dyv1;
    float ny = dxv2*dyv0 - dxv0*dyv2;
    float nz = dxv0*dyv1 - dxv1*dyv0;
    float inv = 1.0f / sqrtf(nx*nx + ny*ny + nz*nz + 1e-12f);

    g_v0[idx] = make_float4(px*d, py*d, d, nx*inv);
    g_n0[idx] = make_float2(ny*inv, nz*inv);
}

// (I0, gx, gy, 0) per channel, planar float4
__global__ void gradpack_kernel(const float* __restrict__ I0) {
    int idx = blockIdx.x * blockDim.x + threadIdx.x;
    if (idx >= BB*CC*HWs) return;
    int p = idx % HWs;
    int h = p / WW, w = p % WW;
    int base = idx - p;
    int xm = (w > 0)    ? w-1 : 0;
    int xp = (w < WW-1) ? w+1 : WW-1;
    int ym = (h > 0)    ? h-1 : 0;
    int yp = (h < HH-1) ? h+1 : HH-1;
    float gx = (I0[base + h*WW + xp] - I0[base + h*WW + xm]) * 0.5f;
    float gy = (I0[base + yp*WW + w] - I0[base + ym*WW + w]) * 0.5f;
    g_ip[idx] = make_float4(I0[idx], gx, gy, 0.0f);
}

// ============================================================
// Accumulate kernel
// ============================================================
__global__ void __launch_bounds__(TPB, 3)
accumulate_kernel(const float* __restrict__ I1,
                  const float* __restrict__ depth0,
                  const float* __restrict__ depth1,
                  const float* __restrict__ intr) {
    int b = blockIdx.y;
    float fx = intr[b*4+0], fy = intr[b*4+1], cx = intr[b*4+2], cy = intr[b*4+3];
    float R00 = g_pose[b*16+0], R01 = g_pose[b*16+1], R02 = g_pose[b*16+2],  t0 = g_pose[b*16+3];
    float R10 = g_pose[b*16+4], R11 = g_pose[b*16+5], R12 = g_pose[b*16+6],  t1 = g_pose[b*16+7];
    float R20 = g_pose[b*16+8], R21 = g_pose[b*16+9], R22 = g_pose[b*16+10], t2 = g_pose[b*16+11];

    float acc[27];
    #pragma unroll
    for (int i = 0; i < 27; i++) acc[i] = 0.0f;

    const float4* v0b = g_v0 + (size_t)b*HWs;
    const float2* n0b = g_n0 + (size_t)b*HWs;
    const float4* ipb = g_ip + (size_t)b*CC*HWs;
    const float*  I1b = I1 + (size_t)b*CC*HWs;

    for (int k = 0; k < PPT; k++) {
        int p  = (blockIdx.x * PPT + k) * TPB + threadIdx.x;
        int hh = p / WW, wwp = p % WW;
        float d0 = depth0[(size_t)b*HWs + p];
        float d1 = depth1[(size_t)b*HWs + p];
        float pxv = ((float)wwp - cx) / fx;
        float pyv = ((float)hh  - cy) / fy;
        float v1x = pxv * d1, v1y = pyv * d1, v1z = d1;

        float x = R00*v1x + R01*v1y + R02*v1z + t0;
        float y = R10*v1x + R11*v1y + R12*v1z + t1;
        float z = R20*v1x + R21*v1y + R22*v1z + t2;

        bool valid0 = z > 1e-8f;
        float zs = (fabsf(z) > 1e-8f) ? z : 1e-8f;
        float u = fx * x / zs + cx;
        float v = fy * y / zs + cy;
        bool inb = (u > 0.0f) && (u < (float)(WW-1)) && (v > 0.0f) && (v < (float)(HH-1));
        if (!(inb && valid0 && (d0 > 0.0f) && (d1 > 0.0f))) continue;

        float u0f = floorf(u), v0f = floorf(v);
        float du = u - u0f, dv = v - v0f;
        int o00 = (int)v0f*WW + (int)u0f;
        int o10 = o00 + WW;
        float wa = (1.0f-du)*(1.0f-dv);
        float wb = du*(1.0f-dv);
        float wc = (1.0f-du)*dv;
        float wd = du*dv;

        // ---------------- ICP row ----------------
        {
            float4 a00 = v0b[o00], a01 = v0b[o00+1], a10 = v0b[o10], a11 = v0b[o10+1];
            float2 b00 = n0b[o00], b01 = n0b[o00+1], b10 = n0b[o10], b11 = n0b[o10+1];
            float rVx = wa*a00.x + wb*a01.x + wc*a10.x + wd*a11.x;
            float rVy = wa*a00.y + wb*a01.y + wc*a10.y + wd*a11.y;
            float rVz = wa*a00.z + wb*a01.z + wc*a10.z + wd*a11.z;
            float rNx = wa*a00.w + wb*a01.w + wc*a10.w + wd*a11.w;
            float rNy = wa*b00.x + wb*b01.x + wc*b10.x + wd*b11.x;
            float rNz = wa*b00.y + wb*b01.y + wc*b10.y + wd*b11.y;

            float dx_ = x - rVx, dy_ = y - rVy, dz_ = z - rVz;
            float dn = sqrtf(dx_*dx_ + dy_*dy_ + dz_*dz_ + 1e-12f);
            bool occ = dn > 0.1f;
            float res_raw = rNx*dx_ + rNy*dy_ + rNz*dz_;
            float N0_ = rNx*R00 + rNy*R10 + rNz*R20;
            float N1_ = rNx*R01 + rNy*R11 + rNz*R21;
            float N2_ = rNx*R02 + rNy*R12 + rNz*R22;
            const float focal = 525.0f, sxy = 5.5f, sdisp = 0.4f, baseline = 1.2f;
            float sd0 = d1 / focal * sxy;
            float sd2 = d1 * d1 * sdisp / (focal * baseline);
            float cov = (N0_*N0_ + N1_*N1_) * (sd0*sd0) + N2_*N2_*(sd2*sd2);
            float sigma = sqrtf(cov + 1e-8f);
            float sden = sigma + 1e-8f;
            float res = res_raw / sden;
            if (occ) res = 1e-6f;
            float Jr0 =  N1_*v1z - N2_*v1y;
            float Jr1 = -N0_*v1z + N2_*v1x;
            float Jr2 =  N0_*v1y - N1_*v1x;
            float sc = GEOM_W / sden;
            float Ji[6];
            Ji[0] = -Jr0*sc;  Ji[1] = -Jr1*sc;  Ji[2] = -Jr2*sc;
            Ji[3] =  N0_*sc;  Ji[4] =  N1_*sc;  Ji[5] =  N2_*sc;
            float ri = -GEOM_W * res;
            float ar  = fabsf(ri);
            float wgt = (ar <= HUBER_DELTA) ? 1.0f : HUBER_DELTA / fmaxf(ar, 1e-12f);
            float wr  = wgt * ri;
            int kk = 0;
            #pragma unroll
            for (int i = 0; i < 6; i++) {
                float wJi = wgt * Ji[i];
                #pragma unroll
                for (int j = i; j < 6; j++) acc[kk++] += wJi * Ji[j];
                acc[21+i] += wr * Ji[i];
            }
        }

        // ---------------- photometric rows (factored, fused f4 taps) ----------------
        float A2 = 0.0f, Bq2 = 0.0f, C2 = 0.0f, Dd = 0.0f, Ee = 0.0f;
        #pragma unroll
        for (int c = 0; c < CC; c++) {
            const float4* Pc = ipb + (size_t)c*HWs;
            float4 q00 = Pc[o00], q01 = Pc[o00+1], q10 = Pc[o10], q11 = Pc[o10+1];
            float I0w = wa*q00.x + wb*q01.x + wc*q10.x + wd*q11.x;
            float gx  = wa*q00.y + wb*q01.y + wc*q10.y + wd*q11.y;
            float gy  = wa*q00.z + wb*q01.z + wc*q10.z + wd*q11.z;
            float r   = I1b[(size_t)c*HWs + p] - I0w;
            float ar  = fabsf(r);
            float wgt = (ar <= HUBER_DELTA) ? 1.0f : HUBER_DELTA / fmaxf(ar, 1e-12f);
            float wgx = wgt * gx;
            float wgy = wgt * gy;
            A2 += wgx * gx;
            Bq2 += wgx * gy;
            C2 += wgy * gy;
            Dd += wgx * r;
            Ee += wgy * r;
        }
        float a  = fx / zs;
        float bq = -fx * x / (zs*zs);
        float c_ = fy / zs;
        float dq = -fy * y / (zs*zs);
        float Jw0[6] = { bq*y,          a*z - bq*x, -a*y,  a,    0.0f, bq };
        float Jw1[6] = { -c_*z + dq*y, -dq*x,        c_*x, 0.0f, c_,   dq };
        int kk = 0;
        #pragma unroll
        for (int i = 0; i < 6; i++) {
            float a0 = A2*Jw0[i] + Bq2*Jw1[i];
            float a1 = Bq2*Jw0[i] + C2*Jw1[i];
            #pragma unroll
            for (int j = i; j < 6; j++) acc[kk++] += a0*Jw0[j] + a1*Jw1[j];
            acc[21+i] += Dd*Jw0[i] + Ee*Jw1[i];
        }
    }

    // -------- block reduction: float warp shuffles, double across warps --------
    __shared__ float sred[TPB/32][27];
    int warp = threadIdx.x >> 5, lane = threadIdx.x & 31;
    #pragma unroll
    for (int i = 0; i < 27; i++) {
        float val = acc[i];
        #pragma unroll
        for (int o = 16; o > 0; o >>= 1)
            val += __shfl_down_sync(0xffffffffu, val, o);
        if (lane == 0) sred[warp][i] = val;
    }
    __syncthreads();
    if (threadIdx.x < 27) {
        double ss = 0.0;
        #pragma unroll
        for (int w2 = 0; w2 < TPB/32; w2++) ss += (double)sred[w2][threadIdx.x];
        g_part[((size_t)b*NBLK + blockIdx.x)*27 + threadIdx.x] = ss;
    }
}

// ============================================================
// Solve 6x6, SE3 exp, pose composition (one block per batch)
// ============================================================
#define SCH 8
__global__ void solve_kernel() {
    int b = blockIdx.x;
    __shared__ double schunk[SCH][27];
    __shared__ double sa[27];
    int i = threadIdx.x % 27;
    int ch = threadIdx.x / 27;
    if (threadIdx.x < 27*SCH) {
        double s = 0.0;
        const int per = NBLK / SCH;   // 12
        for (int blk = ch*per; blk < (ch+1)*per; blk++)
            s += g_part[((size_t)b*NBLK + blk)*27 + i];
        schunk[ch][i] = s;
    }
    __syncthreads();
    if (threadIdx.x < 27) {
        double s = 0.0;
        #pragma unroll
        for (int c2 = 0; c2 < SCH; c2++) s += schunk[c2][threadIdx.x];
        sa[threadIdx.x] = s;
    }
    __syncthreads();
    if (threadIdx.x != 0) return;

    double M[6][7];
    {
        int k = 0;
        for (int i2 = 0; i2 < 6; i2++)
            for (int j = i2; j < 6; j++) { M[i2][j] = sa[k]; M[j][i2] = sa[k]; k++; }
        for (int i2 = 0; i2 < 6; i2++) { M[i2][i2] += 1e-6; M[i2][6] = sa[21+i2]; }
    }
    for (int col = 0; col < 6; col++) {
        int piv = col; double mx = fabs(M[col][col]);
        for (int r = col+1; r < 6; r++) {
            double v2 = fabs(M[r][col]);
            if (v2 > mx) { mx = v2; piv = r; }
        }
        if (piv != col)
            for (int cc2 = col; cc2 < 7; cc2++) { double tmp = M[col][cc2]; M[col][cc2] = M[piv][cc2]; M[piv][cc2] = tmp; }
        double inv = 1.0 / M[col][col];
        for (int r = col+1; r < 6; r++) {
            double f = M[r][col] * inv;
            for (int cc2 = col; cc2 < 7; cc2++) M[r][cc2] -= f * M[col][cc2];
        }
    }
    double xi[6];
    for (int i2 = 5; i2 >= 0; i2--) {
        double s = M[i2][6];
        for (int j = i2+1; j < 6; j++) s -= M[i2][j] * xi[j];
        xi[i2] = s / M[i2][i2];
    }

    double w0 = xi[0], w1 = xi[1], w2 = xi[2];
    double vv0 = xi[3], vv1 = xi[4], vv2 = xi[5];
    double th2 = w0*w0 + w1*w1 + w2*w2;
    double A, Bc, Cc;
    if (th2 < 1e-8) {
        A  = 1.0 - th2/6.0;
        Bc = 0.5 - th2/24.0;
        Cc = 1.0/6.0 - th2/120.0;
    } else {
        double th = sqrt(th2);
        A  = sin(th) / th;
        Bc = (1.0 - cos(th)) / th2;
        Cc = (th - sin(th)) / (th2 * th);
    }
    double K[3][3] = {{0.0,-w2,w1},{w2,0.0,-w0},{-w1,w0,0.0}};
    double K2[3][3];
    for (int i2 = 0; i2 < 3; i2++)
        for (int j = 0; j < 3; j++)
            K2[i2][j] = K[i2][0]*K[0][j] + K[i2][1]*K[1][j] + K[i2][2]*K[2][j];
    double Re[3][3], Vm[3][3];
    for (int i2 = 0; i2 < 3; i2++)
        for (int j = 0; j < 3; j++) {
            double I_ = (i2 == j) ? 1.0 : 0.0;
            Re[i2][j] = I_ + A*K[i2][j] + Bc*K2[i2][j];
            Vm[i2][j] = I_ + Bc*K[i2][j] + Cc*K2[i2][j];
        }
    double te[3];
    for (int i2 = 0; i2 < 3; i2++)
        te[i2] = Vm[i2][0]*vv0 + Vm[i2][1]*vv1 + Vm[i2][2]*vv2;

    double Ro[3][3], to[3];
    for (int i2 = 0; i2 < 3; i2++) {
        for (int j = 0; j < 3; j++) Ro[i2][j] = (double)g_pose[b*16 + i2*4 + j];
        to[i2] = (double)g_pose[b*16 + i2*4 + 3];
    }
    double Rn[3][3], tn[3];
    for (int i2 = 0; i2 < 3; i2++) {
        for (int j = 0; j < 3; j++)
            Rn[i2][j] = Re[i2][0]*Ro[0][j] + Re[i2][1]*Ro[1][j] + Re[i2][2]*Ro[2][j];
        tn[i2] = Re[i2][0]*to[0] + Re[i2][1]*to[1] + Re[i2][2]*to[2] + te[i2];
    }
    for (int i2 = 0; i2 < 3; i2++) {
        for (int j = 0; j < 3; j++) g_pose[b*16 + i2*4 + j] = (float)Rn[i2][j];
        g_pose[b*16 + i2*4 + 3] = (float)tn[i2];
    }
    g_pose[b*16 + 12] = 0.0f; g_pose[b*16 + 13] = 0.0f;
    g_pose[b*16 + 14] = 0.0f; g_pose[b*16 + 15] = 1.0f;
}

__global__ void copyout_kernel(float* __restrict__ out) {
    int i = threadIdx.x;
    if (i < BB*16) out[i] = g_pose[i];
}

// ============================================================
extern "C" void kernel_launch(void* const* d_in, const int* in_sizes, int n_in,
                              void* d_out, int out_size) {
    const float* pose_in = (const float*)d_in[0];
    const float* I0      = (const float*)d_in[1];
    const float* I1      = (const float*)d_in[2];
    const float* intr    = (const float*)d_in[5];
    const float* depth0  = (const float*)d_in[6];
    const float* depth1  = (const float*)d_in[7];
    float* out = (float*)d_out;

    init_pose_kernel<<<1, 64>>>(pose_in);
    vnpack_kernel<<<(BB*HWs + 255)/256, 256>>>(depth0, intr);
    gradpack_kernel<<<(BB*CC*HWs + 255)/256, 256>>>(I0);

    dim3 agrid(NBLK, BB);
    for (int it = 0; it < 3; it++) {
        accumulate_kernel<<<agrid, TPB>>>(I1, depth0, depth1, intr);
        solve_kernel<<<BB, 256>>>();
    }
    copyout_kernel<<<1, 64>>>(out);
}

// round 7
// speedup vs baseline: 5.8125x; 1.0399x over previous
#include <cuda_runtime.h>
#include <cuda_fp16.h>
#include <math.h>

// Problem constants
#define BB 4
#define CC 8
#define HH 192
#define WW 256
#define HWs (HH*WW)

#define GEOM_W 0.01f
#define HUBER_DELTA 0.5f

// Reduction layout
#define NBLK 192         // blocks per batch
#define TPB  256
#define PPT  1           // NBLK*TPB*PPT == HWs

// -------- persistent device scratch (planar / SoA) --------
__device__ uint2  g_ip  [(size_t)BB*CC*HWs];  // per channel plane: half4 (I0, gx, gy, 0)
__device__ float4 g_v0  [(size_t)BB*HWs];     // plane: V0x,V0y,V0z,N0x
__device__ float2 g_n0  [(size_t)BB*HWs];     // plane: N0y,N0z
__device__ double g_part[BB*NBLK*27];
__device__ float  g_pose[BB*16];

// ============================================================
__global__ void init_pose_kernel(const float* __restrict__ pose_in) {
    int i = threadIdx.x;
    if (i < BB*16) g_pose[i] = pose_in[i];
}

// V0 + N0 planes, computed directly from depth0
__global__ void vnpack_kernel(const float* __restrict__ depth0,
                              const float* __restrict__ intr) {
    int idx = blockIdx.x * blockDim.x + threadIdx.x;
    if (idx >= BB*HWs) return;
    int b = idx / HWs, p = idx % HWs;
    int h = p / WW, w = p % WW;
    float fx = intr[b*4+0], fy = intr[b*4+1], cx = intr[b*4+2], cy = intr[b*4+3];
    float invfx = 1.0f/fx, invfy = 1.0f/fy;

    float px = ((float)w - cx) * invfx;
    float py = ((float)h - cy) * invfy;
    const float* D = depth0 + (size_t)b*HWs;
    float d  = D[p];

    int xm = (w > 0)    ? w-1 : 0;
    int xp = (w < WW-1) ? w+1 : WW-1;
    int ym = (h > 0)    ? h-1 : 0;
    int yp = (h < HH-1) ? h+1 : HH-1;
    float dxm = D[h*WW + xm], dxp = D[h*WW + xp];
    float dym = D[ym*WW + w], dyp = D[yp*WW + w];
    float pxm = ((float)xm - cx) * invfx, pxp = ((float)xp - cx) * invfx;
    float pym = ((float)ym - cy) * invfy, pyp = ((float)yp - cy) * invfy;

    float dxv0 = 0.5f*(pxp*dxp - pxm*dxm);
    float dxv1 = 0.5f*py*(dxp - dxm);
    float dxv2 = 0.5f*(dxp - dxm);
    float dyv0 = 0.5f*px*(dyp - dym);
    float dyv1 = 0.5f*(pyp*dyp - pym*dym);
    float dyv2 = 0.5f*(dyp - dym);

    float nx = dxv1*dyv2 - dxv2*dyv1;
    float ny = dxv2*dyv0 - dxv0*dyv2;
    float nz = dxv0*dyv1 - dxv1*dyv0;
    float inv = 1.0f / sqrtf(nx*nx + ny*ny + nz*nz + 1e-12f);

    g_v0[idx] = make_float4(px*d, py*d, d, nx*inv);
    g_n0[idx] = make_float2(ny*inv, nz*inv);
}

// half4 (I0, gx, gy, 0) per channel, planar
__global__ void gradpack_kernel(const float* __restrict__ I0) {
    int idx = blockIdx.x * blockDim.x + threadIdx.x;
    if (idx >= BB*CC*HWs) return;
    int p = idx % HWs;
    int h = p / WW, w = p % WW;
    int base = idx - p;
    int xm = (w > 0)    ? w-1 : 0;
    int xp = (w < WW-1) ? w+1 : WW-1;
    int ym = (h > 0)    ? h-1 : 0;
    int yp = (h < HH-1) ? h+1 : HH-1;
    float gx = (I0[base + h*WW + xp] - I0[base + h*WW + xm]) * 0.5f;
    float gy = (I0[base + yp*WW + w] - I0[base + ym*WW + w]) * 0.5f;
    __half2 lo = __floats2half2_rn(I0[idx], gx);
    __half2 hi = __floats2half2_rn(gy, 0.0f);
    uint2 q;
    q.x = *(const unsigned int*)&lo;
    q.y = *(const unsigned int*)&hi;
    g_ip[idx] = q;
}

// ============================================================
// Accumulate kernel
// ============================================================
__global__ void __launch_bounds__(TPB, 3)
accumulate_kernel(const float* __restrict__ I1,
                  const float* __restrict__ depth0,
                  const float* __restrict__ depth1,
                  const float* __restrict__ intr) {
    int b = blockIdx.y;
    float fx = intr[b*4+0], fy = intr[b*4+1], cx = intr[b*4+2], cy = intr[b*4+3];
    float R00 = g_pose[b*16+0], R01 = g_pose[b*16+1], R02 = g_pose[b*16+2],  t0 = g_pose[b*16+3];
    float R10 = g_pose[b*16+4], R11 = g_pose[b*16+5], R12 = g_pose[b*16+6],  t1 = g_pose[b*16+7];
    float R20 = g_pose[b*16+8], R21 = g_pose[b*16+9], R22 = g_pose[b*16+10], t2 = g_pose[b*16+11];

    float acc[27];
    #pragma unroll
    for (int i = 0; i < 27; i++) acc[i] = 0.0f;

    const float4* v0b = g_v0 + (size_t)b*HWs;
    const float2* n0b = g_n0 + (size_t)b*HWs;
    const uint2*  ipb = g_ip + (size_t)b*CC*HWs;
    const float*  I1b = I1 + (size_t)b*CC*HWs;

    int p  = blockIdx.x * TPB + threadIdx.x;
    int hh = p / WW, wwp = p % WW;
    float d0 = depth0[(size_t)b*HWs + p];
    float d1 = depth1[(size_t)b*HWs + p];
    float pxv = ((float)wwp - cx) / fx;
    float pyv = ((float)hh  - cy) / fy;
    float v1x = pxv * d1, v1y = pyv * d1, v1z = d1;

    float x = R00*v1x + R01*v1y + R02*v1z + t0;
    float y = R10*v1x + R11*v1y + R12*v1z + t1;
    float z = R20*v1x + R21*v1y + R22*v1z + t2;

    bool valid0 = z > 1e-8f;
    float zs = (fabsf(z) > 1e-8f) ? z : 1e-8f;
    float u = fx * x / zs + cx;
    float v = fy * y / zs + cy;
    bool inb = (u > 0.0f) && (u < (float)(WW-1)) && (v > 0.0f) && (v < (float)(HH-1));
    bool valid = inb && valid0 && (d0 > 0.0f) && (d1 > 0.0f);

    if (valid) {
        float u0f = floorf(u), v0f = floorf(v);
        float du = u - u0f, dv = v - v0f;
        int o00 = (int)v0f*WW + (int)u0f;
        int o10 = o00 + WW;
        float wa = (1.0f-du)*(1.0f-dv);
        float wb = du*(1.0f-dv);
        float wc = (1.0f-du)*dv;
        float wd = du*dv;

        // ---------------- ICP row (fp32 path) ----------------
        {
            float4 a00 = v0b[o00], a01 = v0b[o00+1], a10 = v0b[o10], a11 = v0b[o10+1];
            float2 b00 = n0b[o00], b01 = n0b[o00+1], b10 = n0b[o10], b11 = n0b[o10+1];
            float rVx = wa*a00.x + wb*a01.x + wc*a10.x + wd*a11.x;
            float rVy = wa*a00.y + wb*a01.y + wc*a10.y + wd*a11.y;
            float rVz = wa*a00.z + wb*a01.z + wc*a10.z + wd*a11.z;
            float rNx = wa*a00.w + wb*a01.w + wc*a10.w + wd*a11.w;
            float rNy = wa*b00.x + wb*b01.x + wc*b10.x + wd*b11.x;
            float rNz = wa*b00.y + wb*b01.y + wc*b10.y + wd*b11.y;

            float dx_ = x - rVx, dy_ = y - rVy, dz_ = z - rVz;
            float dn = sqrtf(dx_*dx_ + dy_*dy_ + dz_*dz_ + 1e-12f);
            bool occ = dn > 0.1f;
            float res_raw = rNx*dx_ + rNy*dy_ + rNz*dz_;
            float N0_ = rNx*R00 + rNy*R10 + rNz*R20;
            float N1_ = rNx*R01 + rNy*R11 + rNz*R21;
            float N2_ = rNx*R02 + rNy*R12 + rNz*R22;
            const float focal = 525.0f, sxy = 5.5f, sdisp = 0.4f, baseline = 1.2f;
            float sd0 = d1 / focal * sxy;
            float sd2 = d1 * d1 * sdisp / (focal * baseline);
            float cov = (N0_*N0_ + N1_*N1_) * (sd0*sd0) + N2_*N2_*(sd2*sd2);
            float sigma = sqrtf(cov + 1e-8f);
            float sden = sigma + 1e-8f;
            float res = res_raw / sden;
            if (occ) res = 1e-6f;
            float Jr0 =  N1_*v1z - N2_*v1y;
            float Jr1 = -N0_*v1z + N2_*v1x;
            float Jr2 =  N0_*v1y - N1_*v1x;
            float sc = GEOM_W / sden;
            float Ji[6];
            Ji[0] = -Jr0*sc;  Ji[1] = -Jr1*sc;  Ji[2] = -Jr2*sc;
            Ji[3] =  N0_*sc;  Ji[4] =  N1_*sc;  Ji[5] =  N2_*sc;
            float ri = -GEOM_W * res;
            float ar  = fabsf(ri);
            float wgt = (ar <= HUBER_DELTA) ? 1.0f : HUBER_DELTA / fmaxf(ar, 1e-12f);
            float wr  = wgt * ri;
            int kk = 0;
            #pragma unroll
            for (int i = 0; i < 6; i++) {
                float wJi = wgt * Ji[i];
                #pragma unroll
                for (int j = i; j < 6; j++) acc[kk++] += wJi * Ji[j];
                acc[21+i] += wr * Ji[i];
            }
        }

        // ---------------- photometric rows (factored, half4 taps) ----------------
        float A2 = 0.0f, Bq2 = 0.0f, C2 = 0.0f, Dd = 0.0f, Ee = 0.0f;
        #pragma unroll
        for (int c = 0; c < CC; c++) {
            const uint2* Pc = ipb + (size_t)c*HWs;
            uint2 q00 = Pc[o00], q01 = Pc[o00+1], q10 = Pc[o10], q11 = Pc[o10+1];
            float2 a0 = __half22float2(*(const __half2*)&q00.x);
            float2 a1 = __half22float2(*(const __half2*)&q01.x);
            float2 a2 = __half22float2(*(const __half2*)&q10.x);
            float2 a3 = __half22float2(*(const __half2*)&q11.x);
            float g0 = __low2float(*(const __half2*)&q00.y);
            float g1 = __low2float(*(const __half2*)&q01.y);
            float g2 = __low2float(*(const __half2*)&q10.y);
            float g3 = __low2float(*(const __half2*)&q11.y);
            float I0w = wa*a0.x + wb*a1.x + wc*a2.x + wd*a3.x;
            float gx  = wa*a0.y + wb*a1.y + wc*a2.y + wd*a3.y;
            float gy  = wa*g0   + wb*g1   + wc*g2   + wd*g3;
            float r   = I1b[(size_t)c*HWs + p] - I0w;
            float ar  = fabsf(r);
            float wgt = (ar <= HUBER_DELTA) ? 1.0f : HUBER_DELTA / fmaxf(ar, 1e-12f);
            float wgx = wgt * gx;
            float wgy = wgt * gy;
            A2 += wgx * gx;
            Bq2 += wgx * gy;
            C2 += wgy * gy;
            Dd += wgx * r;
            Ee += wgy * r;
        }
        float a  = fx / zs;
        float bq = -fx * x / (zs*zs);
        float c_ = fy / zs;
        float dq = -fy * y / (zs*zs);
        float Jw0[6] = { bq*y,          a*z - bq*x, -a*y,  a,    0.0f, bq };
        float Jw1[6] = { -c_*z + dq*y, -dq*x,        c_*x, 0.0f, c_,   dq };
        int kk = 0;
        #pragma unroll
        for (int i = 0; i < 6; i++) {
            float a0 = A2*Jw0[i] + Bq2*Jw1[i];
            float a1 = Bq2*Jw0[i] + C2*Jw1[i];
            #pragma unroll
            for (int j = i; j < 6; j++) acc[kk++] += a0*Jw0[j] + a1*Jw1[j];
            acc[21+i] += Dd*Jw0[i] + Ee*Jw1[i];
        }
    }

    // -------- block reduction: float warp shuffles, double across warps --------
    __shared__ float sred[TPB/32][27];
    int warp = threadIdx.x >> 5, lane = threadIdx.x & 31;
    #pragma unroll
    for (int i = 0; i < 27; i++) {
        float val = acc[i];
        #pragma unroll
        for (int o = 16; o > 0; o >>= 1)
            val += __shfl_down_sync(0xffffffffu, val, o);
        if (lane == 0) sred[warp][i] = val;
    }
    __syncthreads();
    if (threadIdx.x < 27) {
        double ss = 0.0;
        #pragma unroll
        for (int w2 = 0; w2 < TPB/32; w2++) ss += (double)sred[w2][threadIdx.x];
        g_part[((size_t)b*NBLK + blockIdx.x)*27 + threadIdx.x] = ss;
    }
}

// ============================================================
// Solve 6x6, SE3 exp, pose composition (one block per batch)
// ============================================================
#define SCH 8
__global__ void solve_kernel() {
    int b = blockIdx.x;
    __shared__ double schunk[SCH][27];
    __shared__ double sa[27];
    int i = threadIdx.x % 27;
    int ch = threadIdx.x / 27;
    if (threadIdx.x < 27*SCH) {
        double s = 0.0;
        const int per = NBLK / SCH;
        for (int blk = ch*per; blk < (ch+1)*per; blk++)
            s += g_part[((size_t)b*NBLK + blk)*27 + i];
        schunk[ch][i] = s;
    }
    __syncthreads();
    if (threadIdx.x < 27) {
        double s = 0.0;
        #pragma unroll
        for (int c2 = 0; c2 < SCH; c2++) s += schunk[c2][threadIdx.x];
        sa[threadIdx.x] = s;
    }
    __syncthreads();
    if (threadIdx.x != 0) return;

    double M[6][7];
    {
        int k = 0;
        for (int i2 = 0; i2 < 6; i2++)
            for (int j = i2; j < 6; j++) { M[i2][j] = sa[k]; M[j][i2] = sa[k]; k++; }
        for (int i2 = 0; i2 < 6; i2++) { M[i2][i2] += 1e-6; M[i2][6] = sa[21+i2]; }
    }
    for (int col = 0; col < 6; col++) {
        int piv = col; double mx = fabs(M[col][col]);
        for (int r = col+1; r < 6; r++) {
            double v2 = fabs(M[r][col]);
            if (v2 > mx) { mx = v2; piv = r; }
        }
        if (piv != col)
            for (int cc2 = col; cc2 < 7; cc2++) { double tmp = M[col][cc2]; M[col][cc2] = M[piv][cc2]; M[piv][cc2] = tmp; }
        double inv = 1.0 / M[col][col];
        for (int r = col+1; r < 6; r++) {
            double f = M[r][col] * inv;
            for (int cc2 = col; cc2 < 7; cc2++) M[r][cc2] -= f * M[col][cc2];
        }
    }
    double xi[6];
    for (int i2 = 5; i2 >= 0; i2--) {
        double s = M[i2][6];
        for (int j = i2+1; j < 6; j++) s -= M[i2][j] * xi[j];
        xi[i2] = s / M[i2][i2];
    }

    double w0 = xi[0], w1 = xi[1], w2 = xi[2];
    double vv0 = xi[3], vv1 = xi[4], vv2 = xi[5];
    double th2 = w0*w0 + w1*w1 + w2*w2;
    double A, Bc, Cc;
    if (th2 < 1e-8) {
        A  = 1.0 - th2/6.0;
        Bc = 0.5 - th2/24.0;
        Cc = 1.0/6.0 - th2/120.0;
    } else {
        double th = sqrt(th2);
        A  = sin(th) / th;
        Bc = (1.0 - cos(th)) / th2;
        Cc = (th - sin(th)) / (th2 * th);
    }
    double K[3][3] = {{0.0,-w2,w1},{w2,0.0,-w0},{-w1,w0,0.0}};
    double K2[3][3];
    for (int i2 = 0; i2 < 3; i2++)
        for (int j = 0; j < 3; j++)
            K2[i2][j] = K[i2][0]*K[0][j] + K[i2][1]*K[1][j] + K[i2][2]*K[2][j];
    double Re[3][3], Vm[3][3];
    for (int i2 = 0; i2 < 3; i2++)
        for (int j = 0; j < 3; j++) {
            double I_ = (i2 == j) ? 1.0 : 0.0;
            Re[i2][j] = I_ + A*K[i2][j] + Bc*K2[i2][j];
            Vm[i2][j] = I_ + Bc*K[i2][j] + Cc*K2[i2][j];
        }
    double te[3];
    for (int i2 = 0; i2 < 3; i2++)
        te[i2] = Vm[i2][0]*vv0 + Vm[i2][1]*vv1 + Vm[i2][2]*vv2;

    double Ro[3][3], to[3];
    for (int i2 = 0; i2 < 3; i2++) {
        for (int j = 0; j < 3; j++) Ro[i2][j] = (double)g_pose[b*16 + i2*4 + j];
        to[i2] = (double)g_pose[b*16 + i2*4 + 3];
    }
    double Rn[3][3], tn[3];
    for (int i2 = 0; i2 < 3; i2++) {
        for (int j = 0; j < 3; j++)
            Rn[i2][j] = Re[i2][0]*Ro[0][j] + Re[i2][1]*Ro[1][j] + Re[i2][2]*Ro[2][j];
        tn[i2] = Re[i2][0]*to[0] + Re[i2][1]*to[1] + Re[i2][2]*to[2] + te[i2];
    }
    for (int i2 = 0; i2 < 3; i2++) {
        for (int j = 0; j < 3; j++) g_pose[b*16 + i2*4 + j] = (float)Rn[i2][j];
        g_pose[b*16 + i2*4 + 3] = (float)tn[i2];
    }
    g_pose[b*16 + 12] = 0.0f; g_pose[b*16 + 13] = 0.0f;
    g_pose[b*16 + 14] = 0.0f; g_pose[b*16 + 15] = 1.0f;
}

__global__ void copyout_kernel(float* __restrict__ out) {
    int i = threadIdx.x;
    if (i < BB*16) out[i] = g_pose[i];
}

// ============================================================
extern "C" void kernel_launch(void* const* d_in, const int* in_sizes, int n_in,
                              void* d_out, int out_size) {
    const float* pose_in = (const float*)d_in[0];
    const float* I0      = (const float*)d_in[1];
    const float* I1      = (const float*)d_in[2];
    const float* intr    = (const float*)d_in[5];
    const float* depth0  = (const float*)d_in[6];
    const float* depth1  = (const float*)d_in[7];
    float* out = (float*)d_out;

    init_pose_kernel<<<1, 64>>>(pose_in);
    vnpack_kernel<<<(BB*HWs + 255)/256, 256>>>(depth0, intr);
    gradpack_kernel<<<(BB*CC*HWs + 255)/256, 256>>>(I0);

    dim3 agrid(NBLK, BB);
    for (int it = 0; it < 3; it++) {
        accumulate_kernel<<<agrid, TPB>>>(I1, depth0, depth1, intr);
        solve_kernel<<<BB, 256>>>();
    }
    copyout_kernel<<<1, 64>>>(out);
}

// round 8
// speedup vs baseline: 6.0393x; 1.0390x over previous
#include <cuda_runtime.h>
#include <cuda_fp16.h>
#include <math.h>

// Problem constants
#define BB 4
#define CC 8
#define HH 192
#define WW 256
#define HWs (HH*WW)

#define GEOM_W 0.01f
#define HUBER_DELTA 0.5f

// Reduction layout
#define NBLK 192         // blocks per batch
#define TPB  256         // NBLK*TPB == HWs

// -------- persistent device scratch (planar / SoA) --------
__device__ uint2  g_ip  [(size_t)BB*CC*HWs];  // per channel plane: half4 (I0, gx, gy, 0)
__device__ float4 g_v0  [(size_t)BB*HWs];     // plane: V0x,V0y,V0z,N0x
__device__ float2 g_n0  [(size_t)BB*HWs];     // plane: N0y,N0z
__device__ double g_part[BB*NBLK*27];
__device__ float  g_pose[BB*16];

// ============================================================
// Fused precompute: pose copy + V0/N0 planes + fp16 grad planes
// ============================================================
__global__ void prep_kernel(const float* __restrict__ pose_in,
                            const float* __restrict__ I0,
                            const float* __restrict__ depth0,
                            const float* __restrict__ intr) {
    int idx = blockIdx.x * blockDim.x + threadIdx.x;
    if (idx >= BB*CC*HWs) return;

    // ---- gradient pack (all BB*CC*HWs threads) ----
    {
        int p = idx % HWs;
        int h = p / WW, w = p % WW;
        int base = idx - p;
        int xm = (w > 0)    ? w-1 : 0;
        int xp = (w < WW-1) ? w+1 : WW-1;
        int ym = (h > 0)    ? h-1 : 0;
        int yp = (h < HH-1) ? h+1 : HH-1;
        float gx = (I0[base + h*WW + xp] - I0[base + h*WW + xm]) * 0.5f;
        float gy = (I0[base + yp*WW + w] - I0[base + ym*WW + w]) * 0.5f;
        __half2 lo = __floats2half2_rn(I0[idx], gx);
        __half2 hi = __floats2half2_rn(gy, 0.0f);
        uint2 q;
        q.x = *(const unsigned int*)&lo;
        q.y = *(const unsigned int*)&hi;
        g_ip[idx] = q;
    }

    // ---- vertex/normal pack (first BB*HWs threads) ----
    if (idx < BB*HWs) {
        int b = idx / HWs, p = idx % HWs;
        int h = p / WW, w = p % WW;
        float fx = intr[b*4+0], fy = intr[b*4+1], cx = intr[b*4+2], cy = intr[b*4+3];
        float invfx = 1.0f/fx, invfy = 1.0f/fy;

        float px = ((float)w - cx) * invfx;
        float py = ((float)h - cy) * invfy;
        const float* D = depth0 + (size_t)b*HWs;
        float d  = D[p];

        int xm = (w > 0)    ? w-1 : 0;
        int xp = (w < WW-1) ? w+1 : WW-1;
        int ym = (h > 0)    ? h-1 : 0;
        int yp = (h < HH-1) ? h+1 : HH-1;
        float dxm = D[h*WW + xm], dxp = D[h*WW + xp];
        float dym = D[ym*WW + w], dyp = D[yp*WW + w];
        float pxm = ((float)xm - cx) * invfx, pxp = ((float)xp - cx) * invfx;
        float pym = ((float)ym - cy) * invfy, pyp = ((float)yp - cy) * invfy;

        float dxv0 = 0.5f*(pxp*dxp - pxm*dxm);
        float dxv1 = 0.5f*py*(dxp - dxm);
        float dxv2 = 0.5f*(dxp - dxm);
        float dyv0 = 0.5f*px*(dyp - dym);
        float dyv1 = 0.5f*(pyp*dyp - pym*dym);
        float dyv2 = 0.5f*(dyp - dym);

        float nx = dxv1*dyv2 - dxv2*dyv1;
        float ny = dxv2*dyv0 - dxv0*dyv2;
        float nz = dxv0*dyv1 - dxv1*dyv0;
        float inv = 1.0f / sqrtf(nx*nx + ny*ny + nz*nz + 1e-12f);

        g_v0[idx] = make_float4(px*d, py*d, d, nx*inv);
        g_n0[idx] = make_float2(ny*inv, nz*inv);
    }

    // ---- pose copy (first 64 threads) ----
    if (idx < BB*16) g_pose[idx] = pose_in[idx];
}

// ============================================================
// Accumulate kernel
// ============================================================
__global__ void __launch_bounds__(TPB, 4)
accumulate_kernel(const float* __restrict__ I1,
                  const float* __restrict__ depth0,
                  const float* __restrict__ depth1,
                  const float* __restrict__ intr) {
    int b = blockIdx.y;
    float fx = intr[b*4+0], fy = intr[b*4+1], cx = intr[b*4+2], cy = intr[b*4+3];
    float R00 = g_pose[b*16+0], R01 = g_pose[b*16+1], R02 = g_pose[b*16+2],  t0 = g_pose[b*16+3];
    float R10 = g_pose[b*16+4], R11 = g_pose[b*16+5], R12 = g_pose[b*16+6],  t1 = g_pose[b*16+7];
    float R20 = g_pose[b*16+8], R21 = g_pose[b*16+9], R22 = g_pose[b*16+10], t2 = g_pose[b*16+11];

    float acc[27];
    #pragma unroll
    for (int i = 0; i < 27; i++) acc[i] = 0.0f;

    const float4* v0b = g_v0 + (size_t)b*HWs;
    const float2* n0b = g_n0 + (size_t)b*HWs;
    const uint2*  ipb = g_ip + (size_t)b*CC*HWs;
    const float*  I1b = I1 + (size_t)b*CC*HWs;

    int p  = blockIdx.x * TPB + threadIdx.x;
    int hh = p / WW, wwp = p % WW;
    float d0 = depth0[(size_t)b*HWs + p];
    float d1 = depth1[(size_t)b*HWs + p];
    float pxv = ((float)wwp - cx) / fx;
    float pyv = ((float)hh  - cy) / fy;
    float v1x = pxv * d1, v1y = pyv * d1, v1z = d1;

    float x = R00*v1x + R01*v1y + R02*v1z + t0;
    float y = R10*v1x + R11*v1y + R12*v1z + t1;
    float z = R20*v1x + R21*v1y + R22*v1z + t2;

    bool valid0 = z > 1e-8f;
    float zs = (fabsf(z) > 1e-8f) ? z : 1e-8f;
    float u = fx * x / zs + cx;
    float v = fy * y / zs + cy;
    bool inb = (u > 0.0f) && (u < (float)(WW-1)) && (v > 0.0f) && (v < (float)(HH-1));
    bool valid = inb && valid0 && (d0 > 0.0f) && (d1 > 0.0f);

    if (valid) {
        float u0f = floorf(u), v0f = floorf(v);
        float du = u - u0f, dv = v - v0f;
        int o00 = (int)v0f*WW + (int)u0f;
        int o10 = o00 + WW;
        float wa = (1.0f-du)*(1.0f-dv);
        float wb = du*(1.0f-dv);
        float wc = (1.0f-du)*dv;
        float wd = du*dv;

        // ---------------- ICP row (fp32 path) ----------------
        {
            float4 a00 = v0b[o00], a01 = v0b[o00+1], a10 = v0b[o10], a11 = v0b[o10+1];
            float2 b00 = n0b[o00], b01 = n0b[o00+1], b10 = n0b[o10], b11 = n0b[o10+1];
            float rVx = wa*a00.x + wb*a01.x + wc*a10.x + wd*a11.x;
            float rVy = wa*a00.y + wb*a01.y + wc*a10.y + wd*a11.y;
            float rVz = wa*a00.z + wb*a01.z + wc*a10.z + wd*a11.z;
            float rNx = wa*a00.w + wb*a01.w + wc*a10.w + wd*a11.w;
            float rNy = wa*b00.x + wb*b01.x + wc*b10.x + wd*b11.x;
            float rNz = wa*b00.y + wb*b01.y + wc*b10.y + wd*b11.y;

            float dx_ = x - rVx, dy_ = y - rVy, dz_ = z - rVz;
            float dn = sqrtf(dx_*dx_ + dy_*dy_ + dz_*dz_ + 1e-12f);
            bool occ = dn > 0.1f;
            float res_raw = rNx*dx_ + rNy*dy_ + rNz*dz_;
            float N0_ = rNx*R00 + rNy*R10 + rNz*R20;
            float N1_ = rNx*R01 + rNy*R11 + rNz*R21;
            float N2_ = rNx*R02 + rNy*R12 + rNz*R22;
            const float focal = 525.0f, sxy = 5.5f, sdisp = 0.4f, baseline = 1.2f;
            float sd0 = d1 / focal * sxy;
            float sd2 = d1 * d1 * sdisp / (focal * baseline);
            float cov = (N0_*N0_ + N1_*N1_) * (sd0*sd0) + N2_*N2_*(sd2*sd2);
            float sigma = sqrtf(cov + 1e-8f);
            float sden = sigma + 1e-8f;
            float res = res_raw / sden;
            if (occ) res = 1e-6f;
            float Jr0 =  N1_*v1z - N2_*v1y;
            float Jr1 = -N0_*v1z + N2_*v1x;
            float Jr2 =  N0_*v1y - N1_*v1x;
            float sc = GEOM_W / sden;
            float Ji[6];
            Ji[0] = -Jr0*sc;  Ji[1] = -Jr1*sc;  Ji[2] = -Jr2*sc;
            Ji[3] =  N0_*sc;  Ji[4] =  N1_*sc;  Ji[5] =  N2_*sc;
            float ri = -GEOM_W * res;
            float ar  = fabsf(ri);
            float wgt = (ar <= HUBER_DELTA) ? 1.0f : HUBER_DELTA / fmaxf(ar, 1e-12f);
            float wr  = wgt * ri;
            int kk = 0;
            #pragma unroll
            for (int i = 0; i < 6; i++) {
                float wJi = wgt * Ji[i];
                #pragma unroll
                for (int j = i; j < 6; j++) acc[kk++] += wJi * Ji[j];
                acc[21+i] += wr * Ji[i];
            }
        }

        // ---------------- photometric rows (factored, half4 taps) ----------------
        float A2 = 0.0f, Bq2 = 0.0f, C2 = 0.0f, Dd = 0.0f, Ee = 0.0f;
        #pragma unroll
        for (int c = 0; c < CC; c++) {
            const uint2* Pc = ipb + (size_t)c*HWs;
            uint2 q00 = Pc[o00], q01 = Pc[o00+1], q10 = Pc[o10], q11 = Pc[o10+1];
            float2 a0 = __half22float2(*(const __half2*)&q00.x);
            float2 a1 = __half22float2(*(const __half2*)&q01.x);
            float2 a2 = __half22float2(*(const __half2*)&q10.x);
            float2 a3 = __half22float2(*(const __half2*)&q11.x);
            float g0 = __low2float(*(const __half2*)&q00.y);
            float g1 = __low2float(*(const __half2*)&q01.y);
            float g2 = __low2float(*(const __half2*)&q10.y);
            float g3 = __low2float(*(const __half2*)&q11.y);
            float I0w = wa*a0.x + wb*a1.x + wc*a2.x + wd*a3.x;
            float gx  = wa*a0.y + wb*a1.y + wc*a2.y + wd*a3.y;
            float gy  = wa*g0   + wb*g1   + wc*g2   + wd*g3;
            float r   = I1b[(size_t)c*HWs + p] - I0w;
            float ar  = fabsf(r);
            float wgt = (ar <= HUBER_DELTA) ? 1.0f : HUBER_DELTA / fmaxf(ar, 1e-12f);
            float wgx = wgt * gx;
            float wgy = wgt * gy;
            A2 += wgx * gx;
            Bq2 += wgx * gy;
            C2 += wgy * gy;
            Dd += wgx * r;
            Ee += wgy * r;
        }
        float a  = fx / zs;
        float bq = -fx * x / (zs*zs);
        float c_ = fy / zs;
        float dq = -fy * y / (zs*zs);
        float Jw0[6] = { bq*y,          a*z - bq*x, -a*y,  a,    0.0f, bq };
        float Jw1[6] = { -c_*z + dq*y, -dq*x,        c_*x, 0.0f, c_,   dq };
        int kk = 0;
        #pragma unroll
        for (int i = 0; i < 6; i++) {
            float a0 = A2*Jw0[i] + Bq2*Jw1[i];
            float a1 = Bq2*Jw0[i] + C2*Jw1[i];
            #pragma unroll
            for (int j = i; j < 6; j++) acc[kk++] += a0*Jw0[j] + a1*Jw1[j];
            acc[21+i] += Dd*Jw0[i] + Ee*Jw1[i];
        }
    }

    // -------- block reduction: float warp shuffles, double across warps --------
    __shared__ float sred[TPB/32][27];
    int warp = threadIdx.x >> 5, lane = threadIdx.x & 31;
    #pragma unroll
    for (int i = 0; i < 27; i++) {
        float val = acc[i];
        #pragma unroll
        for (int o = 16; o > 0; o >>= 1)
            val += __shfl_down_sync(0xffffffffu, val, o);
        if (lane == 0) sred[warp][i] = val;
    }
    __syncthreads();
    if (threadIdx.x < 27) {
        double ss = 0.0;
        #pragma unroll
        for (int w2 = 0; w2 < TPB/32; w2++) ss += (double)sred[w2][threadIdx.x];
        g_part[((size_t)b*NBLK + blockIdx.x)*27 + threadIdx.x] = ss;
    }
}

// ============================================================
// Solve 6x6, SE3 exp, pose composition (one block per batch)
// last iteration also writes the output
// ============================================================
#define SCH 8
__global__ void solve_kernel(float* __restrict__ out, int write_out) {
    int b = blockIdx.x;
    __shared__ double schunk[SCH][27];
    __shared__ double sa[27];
    int i = threadIdx.x % 27;
    int ch = threadIdx.x / 27;
    if (threadIdx.x < 27*SCH) {
        double s = 0.0;
        const int per = NBLK / SCH;
        for (int blk = ch*per; blk < (ch+1)*per; blk++)
            s += g_part[((size_t)b*NBLK + blk)*27 + i];
        schunk[ch][i] = s;
    }
    __syncthreads();
    if (threadIdx.x < 27) {
        double s = 0.0;
        #pragma unroll
        for (int c2 = 0; c2 < SCH; c2++) s += schunk[c2][threadIdx.x];
        sa[threadIdx.x] = s;
    }
    __syncthreads();
    if (threadIdx.x == 0) {
        double M[6][7];
        {
            int k = 0;
            for (int i2 = 0; i2 < 6; i2++)
                for (int j = i2; j < 6; j++) { M[i2][j] = sa[k]; M[j][i2] = sa[k]; k++; }
            for (int i2 = 0; i2 < 6; i2++) { M[i2][i2] += 1e-6; M[i2][6] = sa[21+i2]; }
        }
        for (int col = 0; col < 6; col++) {
            int piv = col; double mx = fabs(M[col][col]);
            for (int r = col+1; r < 6; r++) {
                double v2 = fabs(M[r][col]);
                if (v2 > mx) { mx = v2; piv = r; }
            }
            if (piv != col)
                for (int cc2 = col; cc2 < 7; cc2++) { double tmp = M[col][cc2]; M[col][cc2] = M[piv][cc2]; M[piv][cc2] = tmp; }
            double inv = 1.0 / M[col][col];
            for (int r = col+1; r < 6; r++) {
                double f = M[r][col] * inv;
                for (int cc2 = col; cc2 < 7; cc2++) M[r][cc2] -= f * M[col][cc2];
            }
        }
        double xi[6];
        for (int i2 = 5; i2 >= 0; i2--) {
            double s = M[i2][6];
            for (int j = i2+1; j < 6; j++) s -= M[i2][j] * xi[j];
            xi[i2] = s / M[i2][i2];
        }

        double w0 = xi[0], w1 = xi[1], w2 = xi[2];
        double vv0 = xi[3], vv1 = xi[4], vv2 = xi[5];
        double th2 = w0*w0 + w1*w1 + w2*w2;
        double A, Bc, Cc;
        if (th2 < 1e-8) {
            A  = 1.0 - th2/6.0;
            Bc = 0.5 - th2/24.0;
            Cc = 1.0/6.0 - th2/120.0;
        } else {
            double th = sqrt(th2);
            A  = sin(th) / th;
            Bc = (1.0 - cos(th)) / th2;
            Cc = (th - sin(th)) / (th2 * th);
        }
        double K[3][3] = {{0.0,-w2,w1},{w2,0.0,-w0},{-w1,w0,0.0}};
        double K2[3][3];
        for (int i2 = 0; i2 < 3; i2++)
            for (int j = 0; j < 3; j++)
                K2[i2][j] = K[i2][0]*K[0][j] + K[i2][1]*K[1][j] + K[i2][2]*K[2][j];
        double Re[3][3], Vm[3][3];
        for (int i2 = 0; i2 < 3; i2++)
            for (int j = 0; j < 3; j++) {
                double I_ = (i2 == j) ? 1.0 : 0.0;
                Re[i2][j] = I_ + A*K[i2][j] + Bc*K2[i2][j];
                Vm[i2][j] = I_ + Bc*K[i2][j] + Cc*K2[i2][j];
            }
        double te[3];
        for (int i2 = 0; i2 < 3; i2++)
            te[i2] = Vm[i2][0]*vv0 + Vm[i2][1]*vv1 + Vm[i2][2]*vv2;

        double Ro[3][3], to[3];
        for (int i2 = 0; i2 < 3; i2++) {
            for (int j = 0; j < 3; j++) Ro[i2][j] = (double)g_pose[b*16 + i2*4 + j];
            to[i2] = (double)g_pose[b*16 + i2*4 + 3];
        }
        double Rn[3][3], tn[3];
        for (int i2 = 0; i2 < 3; i2++) {
            for (int j = 0; j < 3; j++)
                Rn[i2][j] = Re[i2][0]*Ro[0][j] + Re[i2][1]*Ro[1][j] + Re[i2][2]*Ro[2][j];
            tn[i2] = Re[i2][0]*to[0] + Re[i2][1]*to[1] + Re[i2][2]*to[2] + te[i2];
        }
        for (int i2 = 0; i2 < 3; i2++) {
            for (int j = 0; j < 3; j++) g_pose[b*16 + i2*4 + j] = (float)Rn[i2][j];
            g_pose[b*16 + i2*4 + 3] = (float)tn[i2];
        }
        g_pose[b*16 + 12] = 0.0f; g_pose[b*16 + 13] = 0.0f;
        g_pose[b*16 + 14] = 0.0f; g_pose[b*16 + 15] = 1.0f;
    }
    __syncthreads();
    if (write_out && threadIdx.x < 16)
        out[b*16 + threadIdx.x] = g_pose[b*16 + threadIdx.x];
}

// ============================================================
extern "C" void kernel_launch(void* const* d_in, const int* in_sizes, int n_in,
                              void* d_out, int out_size) {
    const float* pose_in = (const float*)d_in[0];
    const float* I0      = (const float*)d_in[1];
    const float* I1      = (const float*)d_in[2];
    const float* intr    = (const float*)d_in[5];
    const float* depth0  = (const float*)d_in[6];
    const float* depth1  = (const float*)d_in[7];
    float* out = (float*)d_out;

    prep_kernel<<<(BB*CC*HWs + 255)/256, 256>>>(pose_in, I0, depth0, intr);

    dim3 agrid(NBLK, BB);
    for (int it = 0; it < 3; it++) {
        accumulate_kernel<<<agrid, TPB>>>(I1, depth0, depth1, intr);
        solve_kernel<<<BB, 256>>>(out, it == 2 ? 1 : 0);
    }
}

// round 11
// speedup vs baseline: 6.0782x; 1.0064x over previous
#include <cuda_runtime.h>
#include <cuda_fp16.h>
#include <math.h>

// Problem constants
#define BB 4
#define CC 8
#define HH 192
#define WW 256
#define HWs (HH*WW)

#define GEOM_W 0.01f
#define HUBER_DELTA 0.5f

// Reduction layout
#define NBLK 192         // blocks per batch
#define TPB  256         // NBLK*TPB == HWs

// -------- persistent device scratch (planar / SoA) --------
// channel-pair planes: uint4 = half8 (I0_e, gx_e, gy_e, I0_o, gx_o, gy_o, 0, 0)
__device__ uint4  g_ipp [(size_t)BB*4*HWs];
// I1 own-pixel pack: half8 = all 8 channels
__device__ uint4  g_i1p [(size_t)BB*HWs];
__device__ float4 g_v0  [(size_t)BB*HWs];     // V0x,V0y,V0z,N0x (fp32)
__device__ float2 g_n0  [(size_t)BB*HWs];     // N0y,N0z (fp32)
__device__ double g_part[BB*NBLK*27];
__device__ float  g_pose[BB*16];

static __device__ __forceinline__ unsigned h2u(__half2 h) {
    return *(unsigned int*)&h;
}

// ============================================================
// Fused precompute
// ============================================================
__global__ void prep_kernel(const float* __restrict__ pose_in,
                            const float* __restrict__ I0,
                            const float* __restrict__ I1,
                            const float* __restrict__ depth0,
                            const float* __restrict__ intr) {
    int idx = blockIdx.x * blockDim.x + threadIdx.x;
    if (idx >= BB*4*HWs) return;

    // ---- channel-pair gradient pack ----
    {
        int b  = idx / (4*HWs);
        int rem = idx - b*4*HWs;
        int cp = rem / HWs;
        int p  = rem % HWs;
        int h = p / WW, w = p % WW;
        int xm = (w > 0)    ? w-1 : 0;
        int xp = (w < WW-1) ? w+1 : WW-1;
        int ym = (h > 0)    ? h-1 : 0;
        int yp = (h < HH-1) ? h+1 : HH-1;

        float iv[2], gx[2], gy[2];
        #pragma unroll
        for (int e = 0; e < 2; e++) {
            int c = 2*cp + e;
            const float* P = I0 + ((size_t)b*CC + c)*HWs;
            iv[e] = P[p];
            gx[e] = (P[h*WW + xp] - P[h*WW + xm]) * 0.5f;
            gy[e] = (P[yp*WW + w] - P[ym*WW + w]) * 0.5f;
        }
        uint4 q;
        q.x = h2u(__floats2half2_rn(iv[0], gx[0]));
        q.y = h2u(__floats2half2_rn(gy[0], iv[1]));
        q.z = h2u(__floats2half2_rn(gx[1], gy[1]));
        q.w = 0u;
        g_ipp[idx] = q;
    }

    // ---- I1 pack + vertex/normal pack (first BB*HWs threads) ----
    if (idx < BB*HWs) {
        int b = idx / HWs, p = idx % HWs;
        // I1 half8
        {
            const float* P = I1 + (size_t)b*CC*HWs + p;
            uint4 q;
            q.x = h2u(__floats2half2_rn(P[0*HWs], P[1*HWs]));
            q.y = h2u(__floats2half2_rn(P[2*HWs], P[3*HWs]));
            q.z = h2u(__floats2half2_rn(P[4*HWs], P[5*HWs]));
            q.w = h2u(__floats2half2_rn(P[6*HWs], P[7*HWs]));
            g_i1p[idx] = q;
        }
        // V0/N0
        int h = p / WW, w = p % WW;
        float fx = intr[b*4+0], fy = intr[b*4+1], cx = intr[b*4+2], cy = intr[b*4+3];
        float invfx = 1.0f/fx, invfy = 1.0f/fy;

        float px = ((float)w - cx) * invfx;
        float py = ((float)h - cy) * invfy;
        const float* D = depth0 + (size_t)b*HWs;
        float d  = D[p];

        int xm = (w > 0)    ? w-1 : 0;
        int xp = (w < WW-1) ? w+1 : WW-1;
        int ym = (h > 0)    ? h-1 : 0;
        int yp = (h < HH-1) ? h+1 : HH-1;
        float dxm = D[h*WW + xm], dxp = D[h*WW + xp];
        float dym = D[ym*WW + w], dyp = D[yp*WW + w];
        float pxm = ((float)xm - cx) * invfx, pxp = ((float)xp - cx) * invfx;
        float pym = ((float)ym - cy) * invfy, pyp = ((float)yp - cy) * invfy;

        float dxv0 = 0.5f*(pxp*dxp - pxm*dxm);
        float dxv1 = 0.5f*py*(dxp - dxm);
        float dxv2 = 0.5f*(dxp - dxm);
        float dyv0 = 0.5f*px*(dyp - dym);
        float dyv1 = 0.5f*(pyp*dyp - pym*dym);
        float dyv2 = 0.5f*(dyp - dym);

        float nx = dxv1*dyv2 - dxv2*dyv1;
        float ny = dxv2*dyv0 - dxv0*dyv2;
        float nz = dxv0*dyv1 - dxv1*dyv0;
        float inv = 1.0f / sqrtf(nx*nx + ny*ny + nz*nz + 1e-12f);

        g_v0[idx] = make_float4(px*d, py*d, d, nx*inv);
        g_n0[idx] = make_float2(ny*inv, nz*inv);
    }

    if (idx < BB*16) g_pose[idx] = pose_in[idx];
}

// ============================================================
// Accumulate kernel
// ============================================================
__global__ void __launch_bounds__(TPB, 4)
accumulate_kernel(const float* __restrict__ depth0,
                  const float* __restrict__ depth1,
                  const float* __restrict__ intr) {
    int b = blockIdx.y;
    float fx = intr[b*4+0], fy = intr[b*4+1], cx = intr[b*4+2], cy = intr[b*4+3];
    float R00 = g_pose[b*16+0], R01 = g_pose[b*16+1], R02 = g_pose[b*16+2],  t0 = g_pose[b*16+3];
    float R10 = g_pose[b*16+4], R11 = g_pose[b*16+5], R12 = g_pose[b*16+6],  t1 = g_pose[b*16+7];
    float R20 = g_pose[b*16+8], R21 = g_pose[b*16+9], R22 = g_pose[b*16+10], t2 = g_pose[b*16+11];

    float acc[27];
    #pragma unroll
    for (int i = 0; i < 27; i++) acc[i] = 0.0f;

    const float4* v0b = g_v0 + (size_t)b*HWs;
    const float2* n0b = g_n0 + (size_t)b*HWs;
    const uint4*  ippb = g_ipp + (size_t)b*4*HWs;

    int p  = blockIdx.x * TPB + threadIdx.x;
    int hh = p / WW, wwp = p % WW;
    float d0 = depth0[(size_t)b*HWs + p];
    float d1 = depth1[(size_t)b*HWs + p];
    float pxv = ((float)wwp - cx) / fx;
    float pyv = ((float)hh  - cy) / fy;
    float v1x = pxv * d1, v1y = pyv * d1, v1z = d1;

    float x = R00*v1x + R01*v1y + R02*v1z + t0;
    float y = R10*v1x + R11*v1y + R12*v1z + t1;
    float z = R20*v1x + R21*v1y + R22*v1z + t2;

    bool valid0 = z > 1e-8f;
    float zs = (fabsf(z) > 1e-8f) ? z : 1e-8f;
    float u = fx * x / zs + cx;
    float v = fy * y / zs + cy;
    bool inb = (u > 0.0f) && (u < (float)(WW-1)) && (v > 0.0f) && (v < (float)(HH-1));
    bool valid = inb && valid0 && (d0 > 0.0f) && (d1 > 0.0f);

    if (valid) {
        float u0f = floorf(u), v0f = floorf(v);
        float du = u - u0f, dv = v - v0f;
        int o00 = (int)v0f*WW + (int)u0f;
        int o10 = o00 + WW;
        float wa = (1.0f-du)*(1.0f-dv);
        float wb = du*(1.0f-dv);
        float wc = (1.0f-du)*dv;
        float wd = du*dv;

        // ---------------- ICP row (fp32 path) ----------------
        {
            float4 a00 = v0b[o00], a01 = v0b[o00+1], a10 = v0b[o10], a11 = v0b[o10+1];
            float2 b00 = n0b[o00], b01 = n0b[o00+1], b10 = n0b[o10], b11 = n0b[o10+1];
            float rVx = wa*a00.x + wb*a01.x + wc*a10.x + wd*a11.x;
            float rVy = wa*a00.y + wb*a01.y + wc*a10.y + wd*a11.y;
            float rVz = wa*a00.z + wb*a01.z + wc*a10.z + wd*a11.z;
            float rNx = wa*a00.w + wb*a01.w + wc*a10.w + wd*a11.w;
            float rNy = wa*b00.x + wb*b01.x + wc*b10.x + wd*b11.x;
            float rNz = wa*b00.y + wb*b01.y + wc*b10.y + wd*b11.y;

            float dx_ = x - rVx, dy_ = y - rVy, dz_ = z - rVz;
            float dn = sqrtf(dx_*dx_ + dy_*dy_ + dz_*dz_ + 1e-12f);
            bool occ = dn > 0.1f;
            float res_raw = rNx*dx_ + rNy*dy_ + rNz*dz_;
            float N0_ = rNx*R00 + rNy*R10 + rNz*R20;
            float N1_ = rNx*R01 + rNy*R11 + rNz*R21;
            float N2_ = rNx*R02 + rNy*R12 + rNz*R22;
            const float focal = 525.0f, sxy = 5.5f, sdisp = 0.4f, baseline = 1.2f;
            float sd0 = d1 / focal * sxy;
            float sd2 = d1 * d1 * sdisp / (focal * baseline);
            float cov = (N0_*N0_ + N1_*N1_) * (sd0*sd0) + N2_*N2_*(sd2*sd2);
            float sigma = sqrtf(cov + 1e-8f);
            float sden = sigma + 1e-8f;
            float res = res_raw / sden;
            if (occ) res = 1e-6f;
            float Jr0 =  N1_*v1z - N2_*v1y;
            float Jr1 = -N0_*v1z + N2_*v1x;
            float Jr2 =  N0_*v1y - N1_*v1x;
            float sc = GEOM_W / sden;
            float Ji[6];
            Ji[0] = -Jr0*sc;  Ji[1] = -Jr1*sc;  Ji[2] = -Jr2*sc;
            Ji[3] =  N0_*sc;  Ji[4] =  N1_*sc;  Ji[5] =  N2_*sc;
            float ri = -GEOM_W * res;
            float ar  = fabsf(ri);
            float wgt = (ar <= HUBER_DELTA) ? 1.0f : HUBER_DELTA / fmaxf(ar, 1e-12f);
            float wr  = wgt * ri;
            int kk = 0;
            #pragma unroll
            for (int i = 0; i < 6; i++) {
                float wJi = wgt * Ji[i];
                #pragma unroll
                for (int j = i; j < 6; j++) acc[kk++] += wJi * Ji[j];
                acc[21+i] += wr * Ji[i];
            }
        }

        // ---------------- photometric rows (channel-pair packed) ----------------
        uint4 i1q = g_i1p[(size_t)b*HWs + p];
        float2 i1c[4];
        i1c[0] = __half22float2(*(const __half2*)&i1q.x);
        i1c[1] = __half22float2(*(const __half2*)&i1q.y);
        i1c[2] = __half22float2(*(const __half2*)&i1q.z);
        i1c[3] = __half22float2(*(const __half2*)&i1q.w);

        float A2 = 0.0f, Bq2 = 0.0f, C2 = 0.0f, Dd = 0.0f, Ee = 0.0f;
        #pragma unroll
        for (int cp = 0; cp < 4; cp++) {
            const uint4* Pc = ippb + (size_t)cp*HWs;
            uint4 q00 = Pc[o00], q01 = Pc[o00+1], q10 = Pc[o10], q11 = Pc[o10+1];

            float Ie = 0, gxe = 0, gye = 0, Io = 0, gxo = 0, gyo = 0;
            {
                float2 t0_ = __half22float2(*(const __half2*)&q00.x);
                float2 t1_ = __half22float2(*(const __half2*)&q00.y);
                float2 t2_ = __half22float2(*(const __half2*)&q00.z);
                Ie += wa*t0_.x; gxe += wa*t0_.y; gye += wa*t1_.x;
                Io += wa*t1_.y; gxo += wa*t2_.x; gyo += wa*t2_.y;
            }
            {
                float2 t0_ = __half22float2(*(const __half2*)&q01.x);
                float2 t1_ = __half22float2(*(const __half2*)&q01.y);
                float2 t2_ = __half22float2(*(const __half2*)&q01.z);
                Ie += wb*t0_.x; gxe += wb*t0_.y; gye += wb*t1_.x;
                Io += wb*t1_.y; gxo += wb*t2_.x; gyo += wb*t2_.y;
            }
            {
                float2 t0_ = __half22float2(*(const __half2*)&q10.x);
                float2 t1_ = __half22float2(*(const __half2*)&q10.y);
                float2 t2_ = __half22float2(*(const __half2*)&q10.z);
                Ie += wc*t0_.x; gxe += wc*t0_.y; gye += wc*t1_.x;
                Io += wc*t1_.y; gxo += wc*t2_.x; gyo += wc*t2_.y;
            }
            {
                float2 t0_ = __half22float2(*(const __half2*)&q11.x);
                float2 t1_ = __half22float2(*(const __half2*)&q11.y);
                float2 t2_ = __half22float2(*(const __half2*)&q11.z);
                Ie += wd*t0_.x; gxe += wd*t0_.y; gye += wd*t1_.x;
                Io += wd*t1_.y; gxo += wd*t2_.x; gyo += wd*t2_.y;
            }

            // even channel
            {
                float r = i1c[cp].x - Ie;
                float ar  = fabsf(r);
                float wgt = (ar <= HUBER_DELTA) ? 1.0f : HUBER_DELTA / fmaxf(ar, 1e-12f);
                float wgx = wgt * gxe, wgy = wgt * gye;
                A2 += wgx * gxe;  Bq2 += wgx * gye;  C2 += wgy * gye;
                Dd += wgx * r;    Ee += wgy * r;
            }
            // odd channel
            {
                float r = i1c[cp].y - Io;
                float ar  = fabsf(r);
                float wgt = (ar <= HUBER_DELTA) ? 1.0f : HUBER_DELTA / fmaxf(ar, 1e-12f);
                float wgx = wgt * gxo, wgy = wgt * gyo;
                A2 += wgx * gxo;  Bq2 += wgx * gyo;  C2 += wgy * gyo;
                Dd += wgx * r;    Ee += wgy * r;
            }
        }

        float a  = fx / zs;
        float bq = -fx * x / (zs*zs);
        float c_ = fy / zs;
        float dq = -fy * y / (zs*zs);
        float Jw0[6] = { bq*y,          a*z - bq*x, -a*y,  a,    0.0f, bq };
        float Jw1[6] = { -c_*z + dq*y, -dq*x,        c_*x, 0.0f, c_,   dq };
        int kk = 0;
        #pragma unroll
        for (int i = 0; i < 6; i++) {
            float a0 = A2*Jw0[i] + Bq2*Jw1[i];
            float a1 = Bq2*Jw0[i] + C2*Jw1[i];
            #pragma unroll
            for (int j = i; j < 6; j++) acc[kk++] += a0*Jw0[j] + a1*Jw1[j];
            acc[21+i] += Dd*Jw0[i] + Ee*Jw1[i];
        }
    }

    // -------- block reduction: float warp shuffles, double across warps --------
    __shared__ float sred[TPB/32][27];
    int warp = threadIdx.x >> 5, lane = threadIdx.x & 31;
    #pragma unroll
    for (int i = 0; i < 27; i++) {
        float val = acc[i];
        #pragma unroll
        for (int o = 16; o > 0; o >>= 1)
            val += __shfl_down_sync(0xffffffffu, val, o);
        if (lane == 0) sred[warp][i] = val;
    }
    __syncthreads();
    if (threadIdx.x < 27) {
        double ss = 0.0;
        #pragma unroll
        for (int w2 = 0; w2 < TPB/32; w2++) ss += (double)sred[w2][threadIdx.x];
        g_part[((size_t)b*NBLK + blockIdx.x)*27 + threadIdx.x] = ss;
    }
}

// ============================================================
// Solve 6x6, SE3 exp, pose composition (one block per batch)
// ============================================================
#define SCH 8
__global__ void solve_kernel(float* __restrict__ out, int write_out) {
    int b = blockIdx.x;
    __shared__ double schunk[SCH][27];
    __shared__ double sa[27];
    int i = threadIdx.x % 27;
    int ch = threadIdx.x / 27;
    if (threadIdx.x < 27*SCH) {
        double s = 0.0;
        const int per = NBLK / SCH;
        for (int blk = ch*per; blk < (ch+1)*per; blk++)
            s += g_part[((size_t)b*NBLK + blk)*27 + i];
        schunk[ch][i] = s;
    }
    __syncthreads();
    if (threadIdx.x < 27) {
        double s = 0.0;
        #pragma unroll
        for (int c2 = 0; c2 < SCH; c2++) s += schunk[c2][threadIdx.x];
        sa[threadIdx.x] = s;
    }
    __syncthreads();
    if (threadIdx.x == 0) {
        double M[6][7];
        {
            int k = 0;
            for (int i2 = 0; i2 < 6; i2++)
                for (int j = i2; j < 6; j++) { M[i2][j] = sa[k]; M[j][i2] = sa[k]; k++; }
            for (int i2 = 0; i2 < 6; i2++) { M[i2][i2] += 1e-6; M[i2][6] = sa[21+i2]; }
        }
        for (int col = 0; col < 6; col++) {
            int piv = col; double mx = fabs(M[col][col]);
            for (int r = col+1; r < 6; r++) {
                double v2 = fabs(M[r][col]);
                if (v2 > mx) { mx = v2; piv = r; }
            }
            if (piv != col)
                for (int cc2 = col; cc2 < 7; cc2++) { double tmp = M[col][cc2]; M[col][cc2] = M[piv][cc2]; M[piv][cc2] = tmp; }
            double inv = 1.0 / M[col][col];
            for (int r = col+1; r < 6; r++) {
                double f = M[r][col] * inv;
                for (int cc2 = col; cc2 < 7; cc2++) M[r][cc2] -= f * M[col][cc2];
            }
        }
        double xi[6];
        for (int i2 = 5; i2 >= 0; i2--) {
            double s = M[i2][6];
            for (int j = i2+1; j < 6; j++) s -= M[i2][j] * xi[j];
            xi[i2] = s / M[i2][i2];
        }

        double w0 = xi[0], w1 = xi[1], w2 = xi[2];
        double vv0 = xi[3], vv1 = xi[4], vv2 = xi[5];
        double th2 = w0*w0 + w1*w1 + w2*w2;
        double A, Bc, Cc;
        if (th2 < 1e-8) {
            A  = 1.0 - th2/6.0;
            Bc = 0.5 - th2/24.0;
            Cc = 1.0/6.0 - th2/120.0;
        } else {
            double th = sqrt(th2);
            A  = sin(th) / th;
            Bc = (1.0 - cos(th)) / th2;
            Cc = (th - sin(th)) / (th2 * th);
        }
        double K[3][3] = {{0.0,-w2,w1},{w2,0.0,-w0},{-w1,w0,0.0}};
        double K2[3][3];
        for (int i2 = 0; i2 < 3; i2++)
            for (int j = 0; j < 3; j++)
                K2[i2][j] = K[i2][0]*K[0][j] + K[i2][1]*K[1][j] + K[i2][2]*K[2][j];
        double Re[3][3], Vm[3][3];
        for (int i2 = 0; i2 < 3; i2++)
            for (int j = 0; j < 3; j++) {
                double I_ = (i2 == j) ? 1.0 : 0.0;
                Re[i2][j] = I_ + A*K[i2][j] + Bc*K2[i2][j];
                Vm[i2][j] = I_ + Bc*K[i2][j] + Cc*K2[i2][j];
            }
        double te[3];
        for (int i2 = 0; i2 < 3; i2++)
            te[i2] = Vm[i2][0]*vv0 + Vm[i2][1]*vv1 + Vm[i2][2]*vv2;

        double Ro[3][3], to[3];
        for (int i2 = 0; i2 < 3; i2++) {
            for (int j = 0; j < 3; j++) Ro[i2][j] = (double)g_pose[b*16 + i2*4 + j];
            to[i2] = (double)g_pose[b*16 + i2*4 + 3];
        }
        double Rn[3][3], tn[3];
        for (int i2 = 0; i2 < 3; i2++) {
            for (int j = 0; j < 3; j++)
                Rn[i2][j] = Re[i2][0]*Ro[0][j] + Re[i2][1]*Ro[1][j] + Re[i2][2]*Ro[2][j];
            tn[i2] = Re[i2][0]*to[0] + Re[i2][1]*to[1] + Re[i2][2]*to[2] + te[i2];
        }
        for (int i2 = 0; i2 < 3; i2++) {
            for (int j = 0; j < 3; j++) g_pose[b*16 + i2*4 + j] = (float)Rn[i2][j];
            g_pose[b*16 + i2*4 + 3] = (float)tn[i2];
        }
        g_pose[b*16 + 12] = 0.0f; g_pose[b*16 + 13] = 0.0f;
        g_pose[b*16 + 14] = 0.0f; g_pose[b*16 + 15] = 1.0f;
    }
    __syncthreads();
    if (write_out && threadIdx.x < 16)
        out[b*16 + threadIdx.x] = g_pose[b*16 + threadIdx.x];
}

// ============================================================
extern "C" void kernel_launch(void* const* d_in, const int* in_sizes, int n_in,
                              void* d_out, int out_size) {
    const float* pose_in = (const float*)d_in[0];
    const float* I0      = (const float*)d_in[1];
    const float* I1      = (const float*)d_in[2];
    const float* intr    = (const float*)d_in[5];
    const float* depth0  = (const float*)d_in[6];
    const float* depth1  = (const float*)d_in[7];
    float* out = (float*)d_out;

    prep_kernel<<<(BB*4*HWs + 255)/256, 256>>>(pose_in, I0, I1, depth0, intr);

    dim3 agrid(NBLK, BB);
    for (int it = 0; it < 3; it++) {
        accumulate_kernel<<<agrid, TPB>>>(depth0, depth1, intr);
        solve_kernel<<<BB, 256>>>(out, it == 2 ? 1 : 0);
    }
}